// round 8
// baseline (speedup 1.0000x reference)
#include <cuda_runtime.h>
#include <cuda_bf16.h>
#include <math.h>

#define N_NODES   50000
#define N_EDGES   800000
#define D         128
#define N_GRAPHS  64
#define N_CLASSES 10

#define NB 120

// ---------------- scratch ----------------
// Sacrificial pad declared first: if the first/lowest static symbol is broken
// environmentally, this absorbs it.
__device__ float g_pad [1 << 20];                 // 4MB, touched once
__device__ float g_hx  [N_NODES * D + 1024];      // h (fresh name, padded)
__device__ float g_accx[N_NODES * D + 1024];      // aggregation accumulator
__device__ int   g_degx[N_NODES + 256];           // degrees
__device__ float g_pool[N_GRAPHS * D];
__device__ float g_z0  [N_GRAPHS * D];
__device__ int   g_start[N_GRAPHS];
__device__ int   g_end  [N_GRAPHS];

// ---------------- degree: seed self-loop, count dst occurrences ----------------
__global__ void k_seed_deg(int* __restrict__ deg, int n) {
    int stride = gridDim.x * blockDim.x;
    int i0 = blockIdx.x * blockDim.x + threadIdx.x;
    if (i0 == 0) g_pad[0] = 1.0f;                 // keep pad symbol live
    for (int i = i0; i < n; i += stride)
        deg[i] = 1;
}

__global__ void k_count_deg(const int* __restrict__ ei, int* __restrict__ deg, int nE) {
    int stride = gridDim.x * blockDim.x;
    for (int e = blockIdx.x * blockDim.x + threadIdx.x; e < nE; e += stride)
        atomicAdd(&deg[ei[nE + e]], 1);           // planar (2,E): dst = ei[E+e]
}

// ---------------- linear: O[n,128] = A[n,128] @ W[128,128] (k_head1 style) ----------
__global__ void k_lin(const float* __restrict__ A, const float* __restrict__ W,
                      float* __restrict__ O, int nrows) {
    __shared__ float xr[128];
    const int j = threadIdx.x;                    // 128 threads: output feature
    for (int n = blockIdx.x; n < nrows; n += gridDim.x) {
        __syncthreads();
        xr[j] = A[(size_t)n * D + j];
        __syncthreads();
        float acc = 0.f;
#pragma unroll 8
        for (int k = 0; k < 128; k++)
            acc = fmaf(xr[k], __ldg(&W[k * 128 + j]), acc);
        O[(size_t)n * D + j] = acc;
    }
}

// ---------------- zero accumulator ----------------
__global__ void k_zero(float* __restrict__ acc, int n) {
    int stride = gridDim.x * blockDim.x;
    for (int i = blockIdx.x * blockDim.x + threadIdx.x; i < n; i += stride)
        acc[i] = 0.f;
}

// ---------------- edge scatter: acc[dst] += h[src]*rsqrt(deg_s)*rsqrt(deg_d) --------
__global__ void k_scatter(const int* __restrict__ ei, const float* __restrict__ h,
                          float* __restrict__ acc, const int* __restrict__ deg, int nE) {
    int stride = gridDim.x * blockDim.x;
    int total = nE * 32;
    for (int w = blockIdx.x * blockDim.x + threadIdx.x; w < total; w += stride) {
        int e = w >> 5;
        int lane = w & 31;
        int r = __ldg(&ei[e]);
        int c = __ldg(&ei[nE + e]);
        float norm = rsqrtf((float)__ldg(&deg[r])) * rsqrtf((float)__ldg(&deg[c]));
        const float* hp = h + (size_t)r * D + lane * 4;
        float* p = acc + (size_t)c * D + lane * 4;
        atomicAdd(p + 0, hp[0] * norm);
        atomicAdd(p + 1, hp[1] * norm);
        atomicAdd(p + 2, hp[2] * norm);
        atomicAdd(p + 3, hp[3] * norm);
    }
}

// ---------------- finalize: acc = relu(acc + h/deg + b) ----------------
__global__ void k_finalize(const float* __restrict__ h, float* __restrict__ acc,
                           const int* __restrict__ deg, const float* __restrict__ bias,
                           int n) {
    int stride = gridDim.x * blockDim.x;
    for (int i = blockIdx.x * blockDim.x + threadIdx.x; i < n; i += stride) {
        int node = i >> 7;
        int f = i & 127;
        float s = 1.0f / (float)__ldg(&deg[node]);
        float v = fmaf(h[i], s, acc[i]) + __ldg(&bias[f]);
        acc[i] = fmaxf(v, 0.f);
    }
}

// ---------------- segment boundaries from sorted batch ----------------
__global__ void k_bounds(const int* __restrict__ batch, int n) {
    int stride = gridDim.x * blockDim.x;
    for (int i = blockIdx.x * blockDim.x + threadIdx.x; i < n; i += stride) {
        int b = batch[i];
        if (i == 0 || batch[i - 1] != b) g_start[b] = i;
        if (i == n - 1 || batch[i + 1] != b) g_end[b] = i + 1;
    }
}

// ---------------- deterministic max pool: block per graph ----------------
__global__ void k_pool(const float* __restrict__ acc, int ng) {
    int g = blockIdx.x;
    if (g >= ng) return;
    int f = threadIdx.x;
    int s = g_start[g], e = g_end[g];
    float m = -3.402823466e38f;
    for (int n = s; n < e; n++)
        m = fmaxf(m, acc[(size_t)n * D + f]);
    g_pool[g * D + f] = m;
}

// ---------------- head: z0 = relu(pool @ lin0_w + lin0_b) ----------------
__global__ void k_head1(const float* __restrict__ W, const float* __restrict__ b) {
    __shared__ float p[128];
    int g = blockIdx.x;
    int j = threadIdx.x;
    p[j] = g_pool[g * D + j];
    __syncthreads();
    float acc = b[j];
    for (int k = 0; k < 128; k++)
        acc = fmaf(p[k], W[k * 128 + j], acc);
    g_z0[g * D + j] = fmaxf(acc, 0.f);
}

// ---------------- head: out = log_softmax(relu(z0 @ lin1_w + lin1_b)) ----------------
__global__ void k_head2(const float* __restrict__ W, const float* __restrict__ b,
                        float* __restrict__ out) {
    __shared__ float z[128];
    int g = blockIdx.x;
    int t = threadIdx.x;   // 32 threads
#pragma unroll
    for (int i = 0; i < 4; i++) z[t + 32 * i] = g_z0[g * D + t + 32 * i];
    __syncwarp();
    float acc = 0.f;
    if (t < N_CLASSES) {
        acc = b[t];
        for (int k = 0; k < 128; k++)
            acc = fmaf(z[k], W[k * N_CLASSES + t], acc);
        acc = fmaxf(acc, 0.f);
    }
    float vmax = (t < N_CLASSES) ? acc : -3.402823466e38f;
#pragma unroll
    for (int o = 16; o > 0; o >>= 1)
        vmax = fmaxf(vmax, __shfl_xor_sync(0xffffffff, vmax, o));
    float e = (t < N_CLASSES) ? expf(acc - vmax) : 0.f;
    float s = e;
#pragma unroll
    for (int o = 16; o > 0; o >>= 1)
        s += __shfl_xor_sync(0xffffffff, s, o);
    if (t < N_CLASSES)
        out[g * N_CLASSES + t] = acc - vmax - logf(s);
}

// ---------------- launch ----------------
extern "C" void kernel_launch(void* const* d_in, const int* in_sizes, int n_in,
                              void* d_out, int out_size) {
    const float* x = 0; const int* ei = 0; const int* batch = 0;
    const float* w16k[3] = {0,0,0}; int nw = 0;
    const float* b128[3] = {0,0,0}; int nb = 0;
    const float* lin1_w = 0; const float* lin1_b = 0;
    for (int i = 0; i < n_in; i++) {
        int s = in_sizes[i];
        if      (s == N_NODES * D)      x      = (const float*)d_in[i];
        else if (s == 2 * N_EDGES)      ei     = (const int*)  d_in[i];
        else if (s == N_NODES)          batch  = (const int*)  d_in[i];
        else if (s == D * D)            { if (nw < 3) w16k[nw++] = (const float*)d_in[i]; }
        else if (s == D)                { if (nb < 3) b128[nb++] = (const float*)d_in[i]; }
        else if (s == D * N_CLASSES)    lin1_w = (const float*)d_in[i];
        else if (s == N_CLASSES)        lin1_b = (const float*)d_in[i];
    }
    const float* conv0_w = w16k[0];
    const float* conv1_w = w16k[1];
    const float* lin0_w  = w16k[2];
    const float* conv0_b = b128[0];
    const float* conv1_b = b128[1];
    const float* lin0_b  = b128[2];
    float* out = (float*)d_out;

    // Runtime addresses of the big scratch arrays — passed as kernel params so
    // device code uses the same addressing path as the (proven-alive) inputs.
    static float* p_h   = 0;
    static float* p_acc = 0;
    static int*   p_deg = 0;
    if (!p_h) {
        cudaGetSymbolAddress((void**)&p_h,   g_hx);
        cudaGetSymbolAddress((void**)&p_acc, g_accx);
        cudaGetSymbolAddress((void**)&p_deg, g_degx);
    }

    const int nElem = N_NODES * D;     // 6.4M

    // degrees (with self-loop)
    k_seed_deg<<<NB, 256>>>(p_deg, N_NODES);
    k_count_deg<<<NB, 256>>>(ei, p_deg, N_EDGES);

    // conv0
    k_lin<<<NB, 128>>>(x, conv0_w, p_h, N_NODES);
    k_zero<<<NB, 256>>>(p_acc, nElem);
    k_scatter<<<NB, 256>>>(ei, p_h, p_acc, p_deg, N_EDGES);
    k_finalize<<<NB, 256>>>(p_h, p_acc, p_deg, conv0_b, nElem);

    // conv1
    k_lin<<<NB, 128>>>(p_acc, conv1_w, p_h, N_NODES);
    // note: h must be fully written before acc is zeroed (same stream => ordered)
    k_zero<<<NB, 256>>>(p_acc, nElem);
    k_scatter<<<NB, 256>>>(ei, p_h, p_acc, p_deg, N_EDGES);
    k_finalize<<<NB, 256>>>(p_h, p_acc, p_deg, conv1_b, nElem);

    // pool + head
    k_bounds<<<NB, 256>>>(batch, N_NODES);
    k_pool<<<N_GRAPHS, 128>>>(p_acc, N_GRAPHS);
    k_head1<<<N_GRAPHS, 128>>>(lin0_w, lin0_b);
    k_head2<<<N_GRAPHS, 32>>>(lin1_w, lin1_b, out);
}

// round 9
// speedup vs baseline: 6.6144x; 6.6144x over previous
#include <cuda_runtime.h>
#include <cuda_bf16.h>
#include <math.h>

#define N_NODES   50000
#define N_EDGES   800000
#define D         128
#define N_GRAPHS  64
#define N_CLASSES 10
#define POOL_CHUNKS 16

// ---------------- scratch (accessed ONLY via runtime pointers passed as params;
//                  symbol-relative addressing of big arrays proven broken here) ------
__device__ __align__(16) float g_hx  [N_NODES * D + 1024];
__device__ __align__(16) float g_accx[N_NODES * D + 1024];
__device__ __align__(16) int   g_degx[N_NODES + 256];
__device__ __align__(16) float g_poolx[N_GRAPHS * D];
__device__ __align__(16) float g_z0x  [N_GRAPHS * D];
__device__ __align__(16) int   g_startx[N_GRAPHS];
__device__ __align__(16) int   g_endx  [N_GRAPHS];

// ---------------- degree: seed self-loop, count dst occurrences ----------------
__global__ void k_seed_deg(int* __restrict__ deg, float* __restrict__ pool, int n) {
    int i = blockIdx.x * blockDim.x + threadIdx.x;
    if (i < n) deg[i] = 1;
    if (i < N_GRAPHS * D) pool[i] = 0.0f;   // identity for max of relu'd (>=0) values
}

__global__ void k_count_deg(const int* __restrict__ ei, int* __restrict__ deg, int nE) {
    int e = blockIdx.x * blockDim.x + threadIdx.x;
    if (e < nE) atomicAdd(&deg[ei[nE + e]], 1);   // planar (2,E): dst = ei[E+e]
}

// ---------------- GEMM: O[n,128] = A[n,128] @ W[128,128] ----------------
// 64-row tile per block, 256 threads, each thread 8 rows x 4 cols.
__global__ __launch_bounds__(256) void k_gemm(const float* __restrict__ A,
                                              const float* __restrict__ W,
                                              float* __restrict__ O, int nrows) {
    __shared__ float xs[64 * 128];   // 32 KB
    __shared__ float ws[32 * 128];   // 16 KB
    const int tid = threadIdx.x;
    const int rowBase = blockIdx.x * 64;

    float4* xs4 = (float4*)xs;
    float4* ws4 = (float4*)ws;
    const float4* A4 = (const float4*)A;
    const float4* W4 = (const float4*)W;

#pragma unroll
    for (int i = 0; i < 8; i++) {
        int idx = tid + 256 * i;
        int r = rowBase + (idx >> 5);
        xs4[idx] = (r < nrows) ? A4[(size_t)r * 32 + (idx & 31)]
                               : make_float4(0.f, 0.f, 0.f, 0.f);
    }

    const int tx = tid & 31;   // col group: cols [4*tx, 4*tx+3]
    const int ty = tid >> 5;   // row lane: rows ty, ty+8, ..., ty+56
    float acc[8][4];
#pragma unroll
    for (int i = 0; i < 8; i++) { acc[i][0]=acc[i][1]=acc[i][2]=acc[i][3]=0.f; }

    for (int c = 0; c < 4; c++) {       // K chunks of 32
        __syncthreads();
#pragma unroll
        for (int i = 0; i < 4; i++) {
            int idx = tid + 256 * i;
            ws4[idx] = W4[c * 1024 + idx];
        }
        __syncthreads();
#pragma unroll
        for (int k = 0; k < 32; k++) {
            float4 w4 = ws4[k * 32 + tx];
#pragma unroll
            for (int i = 0; i < 8; i++) {
                float xv = xs[(ty + 8 * i) * 128 + c * 32 + k];
                acc[i][0] = fmaf(xv, w4.x, acc[i][0]);
                acc[i][1] = fmaf(xv, w4.y, acc[i][1]);
                acc[i][2] = fmaf(xv, w4.z, acc[i][2]);
                acc[i][3] = fmaf(xv, w4.w, acc[i][3]);
            }
        }
    }

    float4* O4 = (float4*)O;
#pragma unroll
    for (int i = 0; i < 8; i++) {
        int r = rowBase + ty + 8 * i;
        if (r < nrows)
            O4[(size_t)r * 32 + tx] = make_float4(acc[i][0], acc[i][1], acc[i][2], acc[i][3]);
    }
}

// ---------------- seed accumulator with self-loop: acc = h / deg ----------------
__global__ void k_init_acc(const float* __restrict__ h, float* __restrict__ acc,
                           const int* __restrict__ deg, int n4) {
    int idx = blockIdx.x * blockDim.x + threadIdx.x;   // float4 index
    if (idx >= n4) return;
    int node = idx >> 5;
    float s = 1.0f / (float)__ldg(&deg[node]);
    float4 v = ((const float4*)h)[idx];
    v.x *= s; v.y *= s; v.z *= s; v.w *= s;
    ((float4*)acc)[idx] = v;
}

// ---------------- edge scatter: acc[dst] += h[src]*rsqrt(deg_s)*rsqrt(deg_d) --------
// one warp per edge; lane handles 4 consecutive features; vectorized red.
__global__ __launch_bounds__(256) void k_scatter(const int* __restrict__ ei,
                                                 const float* __restrict__ h,
                                                 float* __restrict__ acc,
                                                 const int* __restrict__ deg, int nE) {
    int gthread = blockIdx.x * blockDim.x + threadIdx.x;
    int e = gthread >> 5;
    if (e >= nE) return;
    int lane = threadIdx.x & 31;
    int r = __ldg(&ei[e]);
    int c = __ldg(&ei[nE + e]);
    float norm = rsqrtf((float)__ldg(&deg[r])) * rsqrtf((float)__ldg(&deg[c]));
    float4 v = __ldg(&((const float4*)h)[(size_t)r * 32 + lane]);
    v.x *= norm; v.y *= norm; v.z *= norm; v.w *= norm;
    float* p = acc + (size_t)c * D + lane * 4;
    asm volatile("red.global.add.v4.f32 [%0], {%1, %2, %3, %4};"
                 :: "l"(p), "f"(v.x), "f"(v.y), "f"(v.z), "f"(v.w) : "memory");
}

// ---------------- acc = relu(acc + bias) ----------------
__global__ void k_bias_relu(float* __restrict__ acc, const float* __restrict__ bias,
                            int n4) {
    int idx = blockIdx.x * blockDim.x + threadIdx.x;   // float4 index
    if (idx >= n4) return;
    float4 v = ((const float4*)acc)[idx];
    float4 b = __ldg(&((const float4*)bias)[idx & 31]);
    v.x = fmaxf(v.x + b.x, 0.f);
    v.y = fmaxf(v.y + b.y, 0.f);
    v.z = fmaxf(v.z + b.z, 0.f);
    v.w = fmaxf(v.w + b.w, 0.f);
    ((float4*)acc)[idx] = v;
}

// ---------------- segment boundaries from sorted batch ----------------
__global__ void k_bounds(const int* __restrict__ batch, int* __restrict__ gs,
                         int* __restrict__ ge, int n) {
    int i = blockIdx.x * blockDim.x + threadIdx.x;
    if (i >= n) return;
    int b = batch[i];
    if (i == 0 || batch[i - 1] != b) gs[b] = i;
    if (i == n - 1 || batch[i + 1] != b) ge[b] = i + 1;
}

// ---------------- chunked max pool: grid (graph, chunk); int atomicMax (vals >= 0) ---
__global__ __launch_bounds__(128) void k_pool(const float* __restrict__ acc,
                                              const int* __restrict__ gs,
                                              const int* __restrict__ ge,
                                              float* __restrict__ pool) {
    int g = blockIdx.x;
    int chunk = blockIdx.y;
    int f = threadIdx.x;
    int s = gs[g], e = ge[g];
    int len = e - s;
    int per = (len + POOL_CHUNKS - 1) / POOL_CHUNKS;
    int cs = s + chunk * per;
    int ce = min(cs + per, e);
    if (cs >= ce) return;
    float m = 0.0f;   // values are post-relu >= 0
    for (int n = cs; n < ce; n++)
        m = fmaxf(m, acc[(size_t)n * D + f]);
    atomicMax((int*)&pool[g * D + f], __float_as_int(m));
}

// ---------------- head: z0 = relu(pool @ lin0_w + lin0_b) ----------------
__global__ void k_head1(const float* __restrict__ pool, const float* __restrict__ W,
                        const float* __restrict__ b, float* __restrict__ z0) {
    __shared__ float p[128];
    int g = blockIdx.x;
    int j = threadIdx.x;
    p[j] = pool[g * D + j];
    __syncthreads();
    float acc = b[j];
    for (int k = 0; k < 128; k++)
        acc = fmaf(p[k], __ldg(&W[k * 128 + j]), acc);
    z0[g * D + j] = fmaxf(acc, 0.f);
}

// ---------------- head: out = log_softmax(relu(z0 @ lin1_w + lin1_b)) ----------------
__global__ void k_head2(const float* __restrict__ z0, const float* __restrict__ W,
                        const float* __restrict__ b, float* __restrict__ out) {
    __shared__ float z[128];
    int g = blockIdx.x;
    int t = threadIdx.x;   // 32 threads
#pragma unroll
    for (int i = 0; i < 4; i++) z[t + 32 * i] = z0[g * D + t + 32 * i];
    __syncwarp();
    float acc = 0.f;
    if (t < N_CLASSES) {
        acc = b[t];
        for (int k = 0; k < 128; k++)
            acc = fmaf(z[k], __ldg(&W[k * N_CLASSES + t]), acc);
        acc = fmaxf(acc, 0.f);
    }
    float vmax = (t < N_CLASSES) ? acc : -3.402823466e38f;
#pragma unroll
    for (int o = 16; o > 0; o >>= 1)
        vmax = fmaxf(vmax, __shfl_xor_sync(0xffffffff, vmax, o));
    float e = (t < N_CLASSES) ? expf(acc - vmax) : 0.f;
    float s = e;
#pragma unroll
    for (int o = 16; o > 0; o >>= 1)
        s += __shfl_xor_sync(0xffffffff, s, o);
    if (t < N_CLASSES)
        out[g * N_CLASSES + t] = acc - vmax - logf(s);
}

// ---------------- launch ----------------
extern "C" void kernel_launch(void* const* d_in, const int* in_sizes, int n_in,
                              void* d_out, int out_size) {
    const float* x = 0; const int* ei = 0; const int* batch = 0;
    const float* w16k[3] = {0,0,0}; int nw = 0;
    const float* b128[3] = {0,0,0}; int nb = 0;
    const float* lin1_w = 0; const float* lin1_b = 0;
    for (int i = 0; i < n_in; i++) {
        int s = in_sizes[i];
        if      (s == N_NODES * D)      x      = (const float*)d_in[i];
        else if (s == 2 * N_EDGES)      ei     = (const int*)  d_in[i];
        else if (s == N_NODES)          batch  = (const int*)  d_in[i];
        else if (s == D * D)            { if (nw < 3) w16k[nw++] = (const float*)d_in[i]; }
        else if (s == D)                { if (nb < 3) b128[nb++] = (const float*)d_in[i]; }
        else if (s == D * N_CLASSES)    lin1_w = (const float*)d_in[i];
        else if (s == N_CLASSES)        lin1_b = (const float*)d_in[i];
    }
    const float* conv0_w = w16k[0];
    const float* conv1_w = w16k[1];
    const float* lin0_w  = w16k[2];
    const float* conv0_b = b128[0];
    const float* conv1_b = b128[1];
    const float* lin0_b  = b128[2];
    float* out = (float*)d_out;

    // Runtime addresses for ALL scratch — symbol addressing in device code is
    // broken in this environment (root cause of rounds 1-7).
    static float* p_h = 0; static float* p_acc = 0; static int* p_deg = 0;
    static float* p_pool = 0; static float* p_z0 = 0;
    static int* p_gs = 0; static int* p_ge = 0;
    if (!p_h) {
        cudaGetSymbolAddress((void**)&p_h,    g_hx);
        cudaGetSymbolAddress((void**)&p_acc,  g_accx);
        cudaGetSymbolAddress((void**)&p_deg,  g_degx);
        cudaGetSymbolAddress((void**)&p_pool, g_poolx);
        cudaGetSymbolAddress((void**)&p_z0,   g_z0x);
        cudaGetSymbolAddress((void**)&p_gs,   g_startx);
        cudaGetSymbolAddress((void**)&p_ge,   g_endx);
    }

    const int T = 256;
    const int nF4 = N_NODES * D / 4;          // 1.6M float4
    const int gemm_blocks = (N_NODES + 63) / 64;
    const int scat_blocks = (N_EDGES * 32 + T - 1) / T;

    // degrees (with self-loop) + pool init
    k_seed_deg<<<(N_NODES + T - 1) / T, T>>>(p_deg, p_pool, N_NODES);
    k_count_deg<<<(N_EDGES + T - 1) / T, T>>>(ei, p_deg, N_EDGES);

    // conv0
    k_gemm<<<gemm_blocks, T>>>(x, conv0_w, p_h, N_NODES);
    k_init_acc<<<(nF4 + T - 1) / T, T>>>(p_h, p_acc, p_deg, nF4);
    k_scatter<<<scat_blocks, T>>>(ei, p_h, p_acc, p_deg, N_EDGES);
    k_bias_relu<<<(nF4 + T - 1) / T, T>>>(p_acc, conv0_b, nF4);

    // conv1
    k_gemm<<<gemm_blocks, T>>>(p_acc, conv1_w, p_h, N_NODES);
    k_init_acc<<<(nF4 + T - 1) / T, T>>>(p_h, p_acc, p_deg, nF4);
    k_scatter<<<scat_blocks, T>>>(ei, p_h, p_acc, p_deg, N_EDGES);
    k_bias_relu<<<(nF4 + T - 1) / T, T>>>(p_acc, conv1_b, nF4);

    // pool + head
    k_bounds<<<(N_NODES + T - 1) / T, T>>>(batch, p_gs, p_ge, N_NODES);
    dim3 pg(N_GRAPHS, POOL_CHUNKS);
    k_pool<<<pg, 128>>>(p_acc, p_gs, p_ge, p_pool);
    k_head1<<<N_GRAPHS, 128>>>(p_pool, lin0_w, lin0_b, p_z0);
    k_head2<<<N_GRAPHS, 32>>>(p_z0, lin1_w, lin1_b, out);
}

// round 10
// speedup vs baseline: 8.6163x; 1.3027x over previous
#include <cuda_runtime.h>
#include <cuda_bf16.h>
#include <math.h>

#define N_NODES   50000
#define N_EDGES   800000
#define D         128
#define N_GRAPHS  64
#define N_CLASSES 10
#define POOL_CHUNKS 16
#define SCAN_T 1024

// ---------------- scratch (accessed ONLY via runtime pointers passed as params;
//                  symbol-relative addressing of big arrays proven broken here) ------
__device__ __align__(16) float g_hx  [N_NODES * D + 1024];
__device__ __align__(16) float g_accx[N_NODES * D + 1024];
__device__ __align__(16) int   g_indeg[N_NODES + 256];
__device__ __align__(16) float g_dinvx[N_NODES + 256];
__device__ __align__(16) int   g_offx [N_NODES + 256];     // CSR offsets (N+1 used)
__device__ __align__(16) int   g_curx [N_NODES + 256];     // fill cursors
__device__ __align__(16) int   g_srcx [N_EDGES + 256];     // CSR source ids
__device__ __align__(16) float g_wgtx [N_EDGES + 256];     // CSR edge weights
__device__ __align__(16) float g_poolx[N_GRAPHS * D];
__device__ __align__(16) float g_z0x  [N_GRAPHS * D];
__device__ __align__(16) int   g_startx[N_GRAPHS];
__device__ __align__(16) int   g_endx  [N_GRAPHS];

// ---------------- init: indeg=0, cursors=0, pool=0 ----------------
__global__ void k_seed(int* __restrict__ indeg, int* __restrict__ cur,
                       float* __restrict__ pool, int n) {
    int i = blockIdx.x * blockDim.x + threadIdx.x;
    if (i < n) { indeg[i] = 0; cur[i] = 0; }
    if (i < N_GRAPHS * D) pool[i] = 0.0f;   // identity for max of relu'd (>=0) values
}

__global__ void k_count(const int* __restrict__ ei, int* __restrict__ indeg, int nE) {
    int e = blockIdx.x * blockDim.x + threadIdx.x;
    if (e < nE) atomicAdd(&indeg[ei[nE + e]], 1);   // planar (2,E): dst = ei[E+e]
}

__global__ void k_dinv(const int* __restrict__ indeg, float* __restrict__ dinv, int n) {
    int i = blockIdx.x * blockDim.x + threadIdx.x;
    if (i < n) dinv[i] = rsqrtf((float)(indeg[i] + 1));
}

// ---------------- exclusive scan of indeg -> off (single block) ----------------
__global__ __launch_bounds__(SCAN_T) void k_scan(const int* __restrict__ indeg,
                                                 int* __restrict__ off, int n) {
    __shared__ int sums[SCAN_T];
    int t = threadIdx.x;
    int seg = (n + SCAN_T - 1) / SCAN_T;
    int s0 = t * seg;
    int s1 = min(s0 + seg, n);
    int tot = 0;
    for (int i = s0; i < s1; i++) tot += indeg[i];
    sums[t] = tot;
    __syncthreads();
    for (int o = 1; o < SCAN_T; o <<= 1) {     // inclusive Hillis-Steele
        int v = (t >= o) ? sums[t - o] : 0;
        __syncthreads();
        sums[t] += v;
        __syncthreads();
    }
    int run = (t == 0) ? 0 : sums[t - 1];
    for (int i = s0; i < s1; i++) { off[i] = run; run += indeg[i]; }
    if (t == SCAN_T - 1) off[n] = run;
}

// ---------------- CSR fill: src ids + edge weights ----------------
__global__ void k_fill(const int* __restrict__ ei, const int* __restrict__ off,
                       int* __restrict__ cur, int* __restrict__ src,
                       float* __restrict__ wgt, const float* __restrict__ dinv, int nE) {
    int e = blockIdx.x * blockDim.x + threadIdx.x;
    if (e >= nE) return;
    int r = ei[e];
    int c = ei[nE + e];
    int pos = atomicAdd(&cur[c], 1);
    int j = off[c] + pos;
    src[j] = r;
    wgt[j] = dinv[r] * dinv[c];
}

// ---------------- GEMM: O[n,128] = A[n,128] @ W[128,128] ----------------
__global__ __launch_bounds__(256) void k_gemm(const float* __restrict__ A,
                                              const float* __restrict__ W,
                                              float* __restrict__ O, int nrows) {
    __shared__ float xs[64 * 128];   // 32 KB
    __shared__ float ws[32 * 128];   // 16 KB
    const int tid = threadIdx.x;
    const int rowBase = blockIdx.x * 64;

    float4* xs4 = (float4*)xs;
    float4* ws4 = (float4*)ws;
    const float4* A4 = (const float4*)A;
    const float4* W4 = (const float4*)W;

#pragma unroll
    for (int i = 0; i < 8; i++) {
        int idx = tid + 256 * i;
        int r = rowBase + (idx >> 5);
        xs4[idx] = (r < nrows) ? A4[(size_t)r * 32 + (idx & 31)]
                               : make_float4(0.f, 0.f, 0.f, 0.f);
    }

    const int tx = tid & 31;
    const int ty = tid >> 5;
    float acc[8][4];
#pragma unroll
    for (int i = 0; i < 8; i++) { acc[i][0]=acc[i][1]=acc[i][2]=acc[i][3]=0.f; }

    for (int c = 0; c < 4; c++) {
        __syncthreads();
#pragma unroll
        for (int i = 0; i < 4; i++) {
            int idx = tid + 256 * i;
            ws4[idx] = W4[c * 1024 + idx];
        }
        __syncthreads();
#pragma unroll
        for (int k = 0; k < 32; k++) {
            float4 w4 = ws4[k * 32 + tx];
#pragma unroll
            for (int i = 0; i < 8; i++) {
                float xv = xs[(ty + 8 * i) * 128 + c * 32 + k];
                acc[i][0] = fmaf(xv, w4.x, acc[i][0]);
                acc[i][1] = fmaf(xv, w4.y, acc[i][1]);
                acc[i][2] = fmaf(xv, w4.z, acc[i][2]);
                acc[i][3] = fmaf(xv, w4.w, acc[i][3]);
            }
        }
    }

    float4* O4 = (float4*)O;
#pragma unroll
    for (int i = 0; i < 8; i++) {
        int r = rowBase + ty + 8 * i;
        if (r < nrows)
            O4[(size_t)r * 32 + tx] = make_float4(acc[i][0], acc[i][1], acc[i][2], acc[i][3]);
    }
}

// ---------------- gather-aggregate + self-loop + bias + relu ----------------
// one warp per node; lane handles float4 of features; accumulation in registers.
__global__ __launch_bounds__(256) void k_gather(const float* __restrict__ h,
                                                float* __restrict__ acc,
                                                const int* __restrict__ off,
                                                const int* __restrict__ src,
                                                const float* __restrict__ wgt,
                                                const int* __restrict__ indeg,
                                                const float* __restrict__ bias, int nN) {
    int w = (blockIdx.x * blockDim.x + threadIdx.x) >> 5;
    if (w >= nN) return;
    int lane = threadIdx.x & 31;
    int s = __ldg(&off[w]);
    int e = __ldg(&off[w + 1]);
    const float4* h4 = (const float4*)h;

    // self-loop term: h[w] / deg[w]
    float selfw = 1.0f / (float)(__ldg(&indeg[w]) + 1);
    float4 a = __ldg(&h4[(size_t)w * 32 + lane]);
    a.x *= selfw; a.y *= selfw; a.z *= selfw; a.w *= selfw;
    float4 a2 = make_float4(0.f, 0.f, 0.f, 0.f);

    int j = s;
    for (; j + 1 < e; j += 2) {       // 2-way unroll for MLP
        int   r0 = __ldg(&src[j]);
        int   r1 = __ldg(&src[j + 1]);
        float w0 = __ldg(&wgt[j]);
        float w1 = __ldg(&wgt[j + 1]);
        float4 v0 = __ldg(&h4[(size_t)r0 * 32 + lane]);
        float4 v1 = __ldg(&h4[(size_t)r1 * 32 + lane]);
        a.x  = fmaf(v0.x, w0, a.x);  a.y  = fmaf(v0.y, w0, a.y);
        a.z  = fmaf(v0.z, w0, a.z);  a.w  = fmaf(v0.w, w0, a.w);
        a2.x = fmaf(v1.x, w1, a2.x); a2.y = fmaf(v1.y, w1, a2.y);
        a2.z = fmaf(v1.z, w1, a2.z); a2.w = fmaf(v1.w, w1, a2.w);
    }
    if (j < e) {
        int   r0 = __ldg(&src[j]);
        float w0 = __ldg(&wgt[j]);
        float4 v0 = __ldg(&h4[(size_t)r0 * 32 + lane]);
        a.x = fmaf(v0.x, w0, a.x); a.y = fmaf(v0.y, w0, a.y);
        a.z = fmaf(v0.z, w0, a.z); a.w = fmaf(v0.w, w0, a.w);
    }
    float4 b = __ldg(&((const float4*)bias)[lane]);
    a.x = fmaxf(a.x + a2.x + b.x, 0.f);
    a.y = fmaxf(a.y + a2.y + b.y, 0.f);
    a.z = fmaxf(a.z + a2.z + b.z, 0.f);
    a.w = fmaxf(a.w + a2.w + b.w, 0.f);
    ((float4*)acc)[(size_t)w * 32 + lane] = a;
}

// ---------------- segment boundaries from sorted batch ----------------
__global__ void k_bounds(const int* __restrict__ batch, int* __restrict__ gs,
                         int* __restrict__ ge, int n) {
    int i = blockIdx.x * blockDim.x + threadIdx.x;
    if (i >= n) return;
    int b = batch[i];
    if (i == 0 || batch[i - 1] != b) gs[b] = i;
    if (i == n - 1 || batch[i + 1] != b) ge[b] = i + 1;
}

// ---------------- chunked max pool (values >= 0; int atomicMax) ----------------
__global__ __launch_bounds__(128) void k_pool(const float* __restrict__ acc,
                                              const int* __restrict__ gs,
                                              const int* __restrict__ ge,
                                              float* __restrict__ pool) {
    int g = blockIdx.x;
    int chunk = blockIdx.y;
    int f = threadIdx.x;
    int s = gs[g], e = ge[g];
    int len = e - s;
    int per = (len + POOL_CHUNKS - 1) / POOL_CHUNKS;
    int cs = s + chunk * per;
    int ce = min(cs + per, e);
    if (cs >= ce) return;
    float m = 0.0f;
    for (int n = cs; n < ce; n++)
        m = fmaxf(m, acc[(size_t)n * D + f]);
    atomicMax((int*)&pool[g * D + f], __float_as_int(m));
}

// ---------------- head: z0 = relu(pool @ lin0_w + lin0_b) ----------------
__global__ void k_head1(const float* __restrict__ pool, const float* __restrict__ W,
                        const float* __restrict__ b, float* __restrict__ z0) {
    __shared__ float p[128];
    int g = blockIdx.x;
    int j = threadIdx.x;
    p[j] = pool[g * D + j];
    __syncthreads();
    float acc = b[j];
    for (int k = 0; k < 128; k++)
        acc = fmaf(p[k], __ldg(&W[k * 128 + j]), acc);
    z0[g * D + j] = fmaxf(acc, 0.f);
}

// ---------------- head: out = log_softmax(relu(z0 @ lin1_w + lin1_b)) ----------------
__global__ void k_head2(const float* __restrict__ z0, const float* __restrict__ W,
                        const float* __restrict__ b, float* __restrict__ out) {
    __shared__ float z[128];
    int g = blockIdx.x;
    int t = threadIdx.x;
#pragma unroll
    for (int i = 0; i < 4; i++) z[t + 32 * i] = z0[g * D + t + 32 * i];
    __syncwarp();
    float acc = 0.f;
    if (t < N_CLASSES) {
        acc = b[t];
        for (int k = 0; k < 128; k++)
            acc = fmaf(z[k], __ldg(&W[k * N_CLASSES + t]), acc);
        acc = fmaxf(acc, 0.f);
    }
    float vmax = (t < N_CLASSES) ? acc : -3.402823466e38f;
#pragma unroll
    for (int o = 16; o > 0; o >>= 1)
        vmax = fmaxf(vmax, __shfl_xor_sync(0xffffffff, vmax, o));
    float e = (t < N_CLASSES) ? expf(acc - vmax) : 0.f;
    float s = e;
#pragma unroll
    for (int o = 16; o > 0; o >>= 1)
        s += __shfl_xor_sync(0xffffffff, s, o);
    if (t < N_CLASSES)
        out[g * N_CLASSES + t] = acc - vmax - logf(s);
}

// ---------------- launch ----------------
extern "C" void kernel_launch(void* const* d_in, const int* in_sizes, int n_in,
                              void* d_out, int out_size) {
    const float* x = 0; const int* ei = 0; const int* batch = 0;
    const float* w16k[3] = {0,0,0}; int nw = 0;
    const float* b128[3] = {0,0,0}; int nb = 0;
    const float* lin1_w = 0; const float* lin1_b = 0;
    for (int i = 0; i < n_in; i++) {
        int s = in_sizes[i];
        if      (s == N_NODES * D)      x      = (const float*)d_in[i];
        else if (s == 2 * N_EDGES)      ei     = (const int*)  d_in[i];
        else if (s == N_NODES)          batch  = (const int*)  d_in[i];
        else if (s == D * D)            { if (nw < 3) w16k[nw++] = (const float*)d_in[i]; }
        else if (s == D)                { if (nb < 3) b128[nb++] = (const float*)d_in[i]; }
        else if (s == D * N_CLASSES)    lin1_w = (const float*)d_in[i];
        else if (s == N_CLASSES)        lin1_b = (const float*)d_in[i];
    }
    const float* conv0_w = w16k[0];
    const float* conv1_w = w16k[1];
    const float* lin0_w  = w16k[2];
    const float* conv0_b = b128[0];
    const float* conv1_b = b128[1];
    const float* lin0_b  = b128[2];
    float* out = (float*)d_out;

    // Runtime addresses for ALL scratch (symbol addressing in device code broken here).
    static float* p_h = 0; static float* p_acc = 0; static int* p_ind = 0;
    static float* p_dinv = 0; static int* p_off = 0; static int* p_cur = 0;
    static int* p_src = 0; static float* p_wgt = 0;
    static float* p_pool = 0; static float* p_z0 = 0;
    static int* p_gs = 0; static int* p_ge = 0;
    if (!p_h) {
        cudaGetSymbolAddress((void**)&p_h,    g_hx);
        cudaGetSymbolAddress((void**)&p_acc,  g_accx);
        cudaGetSymbolAddress((void**)&p_ind,  g_indeg);
        cudaGetSymbolAddress((void**)&p_dinv, g_dinvx);
        cudaGetSymbolAddress((void**)&p_off,  g_offx);
        cudaGetSymbolAddress((void**)&p_cur,  g_curx);
        cudaGetSymbolAddress((void**)&p_src,  g_srcx);
        cudaGetSymbolAddress((void**)&p_wgt,  g_wgtx);
        cudaGetSymbolAddress((void**)&p_pool, g_poolx);
        cudaGetSymbolAddress((void**)&p_z0,   g_z0x);
        cudaGetSymbolAddress((void**)&p_gs,   g_startx);
        cudaGetSymbolAddress((void**)&p_ge,   g_endx);
    }

    const int T = 256;
    const int gemm_blocks = (N_NODES + 63) / 64;
    const int gath_blocks = (N_NODES * 32 + T - 1) / T;

    // CSR build
    k_seed <<<(N_NODES + T - 1) / T, T>>>(p_ind, p_cur, p_pool, N_NODES);
    k_count<<<(N_EDGES + T - 1) / T, T>>>(ei, p_ind, N_EDGES);
    k_dinv <<<(N_NODES + T - 1) / T, T>>>(p_ind, p_dinv, N_NODES);
    k_scan <<<1, SCAN_T>>>(p_ind, p_off, N_NODES);
    k_fill <<<(N_EDGES + T - 1) / T, T>>>(ei, p_off, p_cur, p_src, p_wgt, p_dinv, N_EDGES);

    // conv0: h = x@w0 ; acc = relu(agg(h) + b0)
    k_gemm  <<<gemm_blocks, T>>>(x, conv0_w, p_h, N_NODES);
    k_gather<<<gath_blocks, T>>>(p_h, p_acc, p_off, p_src, p_wgt, p_ind, conv0_b, N_NODES);

    // conv1
    k_gemm  <<<gemm_blocks, T>>>(p_acc, conv1_w, p_h, N_NODES);
    k_gather<<<gath_blocks, T>>>(p_h, p_acc, p_off, p_src, p_wgt, p_ind, conv1_b, N_NODES);

    // pool + head
    k_bounds<<<(N_NODES + T - 1) / T, T>>>(batch, p_gs, p_ge, N_NODES);
    dim3 pg(N_GRAPHS, POOL_CHUNKS);
    k_pool<<<pg, 128>>>(p_acc, p_gs, p_ge, p_pool);
    k_head1<<<N_GRAPHS, 128>>>(p_pool, lin0_w, lin0_b, p_z0);
    k_head2<<<N_GRAPHS, 32>>>(p_z0, lin1_w, lin1_b, out);
}

// round 11
// speedup vs baseline: 9.4468x; 1.0964x over previous
#include <cuda_runtime.h>
#include <cuda_bf16.h>
#include <math.h>

#define N_NODES   50000
#define N_EDGES   800000
#define D         128
#define N_GRAPHS  64
#define N_CLASSES 10
#define POOL_CHUNKS 16
#define SCAN_B 256
#define SCAN_NBLK ((N_NODES + SCAN_B - 1) / SCAN_B)   // 196

// ---------------- scratch (accessed ONLY via runtime pointers passed as params;
//                  symbol-relative addressing of big arrays proven broken here) ------
__device__ __align__(16) float g_hx  [N_NODES * D + 1024];
__device__ __align__(16) float g_accx[N_NODES * D + 1024];
__device__ __align__(16) int   g_indeg[N_NODES + 256];
__device__ __align__(16) float g_dinvx[N_NODES + 256];
__device__ __align__(16) int   g_offx [N_NODES + 256];     // CSR offsets (N+1 used)
__device__ __align__(16) int   g_curx [N_NODES + 256];     // fill cursors
__device__ __align__(16) int   g_srcx [N_EDGES + 256];     // CSR source ids
__device__ __align__(16) float g_wgtx [N_EDGES + 256];     // CSR edge weights
__device__ __align__(16) int   g_partx[SCAN_NBLK + 8];     // block partial sums
__device__ __align__(16) float g_poolx[N_GRAPHS * D];
__device__ __align__(16) float g_z0x  [N_GRAPHS * D];
__device__ __align__(16) int   g_startx[N_GRAPHS];
__device__ __align__(16) int   g_endx  [N_GRAPHS];

// ---------------- init: indeg=0, cursors=0, pool=0 ----------------
__global__ void k_seed(int* __restrict__ indeg, int* __restrict__ cur,
                       float* __restrict__ pool, int n) {
    int i = blockIdx.x * blockDim.x + threadIdx.x;
    if (i < n) { indeg[i] = 0; cur[i] = 0; }
    if (i < N_GRAPHS * D) pool[i] = 0.0f;   // identity for max of relu'd (>=0) values
}

__global__ void k_count(const int* __restrict__ ei, int* __restrict__ indeg, int nE) {
    int e = blockIdx.x * blockDim.x + threadIdx.x;
    if (e < nE) atomicAdd(&indeg[ei[nE + e]], 1);   // planar (2,E): dst = ei[E+e]
}

__global__ void k_dinv(const int* __restrict__ indeg, float* __restrict__ dinv, int n) {
    int i = blockIdx.x * blockDim.x + threadIdx.x;
    if (i < n) dinv[i] = rsqrtf((float)(indeg[i] + 1));
}

// ---------------- scan phase 1: per-block sums ----------------
__global__ __launch_bounds__(SCAN_B) void k_part(const int* __restrict__ indeg,
                                                 int* __restrict__ part, int n) {
    __shared__ int sh[SCAN_B];
    int t = threadIdx.x;
    int i = blockIdx.x * SCAN_B + t;
    sh[t] = (i < n) ? indeg[i] : 0;
    __syncthreads();
#pragma unroll
    for (int o = SCAN_B / 2; o > 0; o >>= 1) {
        if (t < o) sh[t] += sh[t + o];
        __syncthreads();
    }
    if (t == 0) part[blockIdx.x] = sh[0];
}

// ---------------- scan phase 2: inclusive scan of partials (1 small block) ----------
__global__ __launch_bounds__(SCAN_B) void k_scanpart(int* __restrict__ part,
                                                     int* __restrict__ off, int nblk, int n) {
    __shared__ int sh[SCAN_B];
    int t = threadIdx.x;
    sh[t] = (t < nblk) ? part[t] : 0;
    __syncthreads();
#pragma unroll
    for (int o = 1; o < SCAN_B; o <<= 1) {
        int v = (t >= o) ? sh[t - o] : 0;
        __syncthreads();
        sh[t] += v;
        __syncthreads();
    }
    if (t < nblk) part[t] = sh[t];          // inclusive sums
    if (t == 0) off[n] = N_EDGES;           // total edges (constant)
}

// ---------------- scan phase 3: in-block exclusive scan + base -> offsets -----------
__global__ __launch_bounds__(SCAN_B) void k_off(const int* __restrict__ indeg,
                                                const int* __restrict__ part,
                                                int* __restrict__ off, int n) {
    __shared__ int sh[SCAN_B];
    int t = threadIdx.x;
    int b = blockIdx.x;
    int i = b * SCAN_B + t;
    int v = (i < n) ? indeg[i] : 0;
    sh[t] = v;
    __syncthreads();
#pragma unroll
    for (int o = 1; o < SCAN_B; o <<= 1) {   // inclusive Hillis-Steele
        int u = (t >= o) ? sh[t - o] : 0;
        __syncthreads();
        sh[t] += u;
        __syncthreads();
    }
    int base = (b == 0) ? 0 : part[b - 1];
    if (i < n) off[i] = base + sh[t] - v;    // exclusive
}

// ---------------- CSR fill: src ids + edge weights ----------------
__global__ void k_fill(const int* __restrict__ ei, const int* __restrict__ off,
                       int* __restrict__ cur, int* __restrict__ src,
                       float* __restrict__ wgt, const float* __restrict__ dinv, int nE) {
    int e = blockIdx.x * blockDim.x + threadIdx.x;
    if (e >= nE) return;
    int r = ei[e];
    int c = ei[nE + e];
    int pos = atomicAdd(&cur[c], 1);
    int j = off[c] + pos;
    src[j] = r;
    wgt[j] = dinv[r] * dinv[c];
}

// ---------------- GEMM: O[n,128] = A[n,128] @ W[128,128] ----------------
__global__ __launch_bounds__(256) void k_gemm(const float* __restrict__ A,
                                              const float* __restrict__ W,
                                              float* __restrict__ O, int nrows) {
    __shared__ float xs[64 * 128];   // 32 KB
    __shared__ float ws[32 * 128];   // 16 KB
    const int tid = threadIdx.x;
    const int rowBase = blockIdx.x * 64;

    float4* xs4 = (float4*)xs;
    float4* ws4 = (float4*)ws;
    const float4* A4 = (const float4*)A;
    const float4* W4 = (const float4*)W;

#pragma unroll
    for (int i = 0; i < 8; i++) {
        int idx = tid + 256 * i;
        int r = rowBase + (idx >> 5);
        xs4[idx] = (r < nrows) ? A4[(size_t)r * 32 + (idx & 31)]
                               : make_float4(0.f, 0.f, 0.f, 0.f);
    }

    const int tx = tid & 31;
    const int ty = tid >> 5;
    float acc[8][4];
#pragma unroll
    for (int i = 0; i < 8; i++) { acc[i][0]=acc[i][1]=acc[i][2]=acc[i][3]=0.f; }

    for (int c = 0; c < 4; c++) {
        __syncthreads();
#pragma unroll
        for (int i = 0; i < 4; i++) {
            int idx = tid + 256 * i;
            ws4[idx] = W4[c * 1024 + idx];
        }
        __syncthreads();
#pragma unroll
        for (int k = 0; k < 32; k++) {
            float4 w4 = ws4[k * 32 + tx];
#pragma unroll
            for (int i = 0; i < 8; i++) {
                float xv = xs[(ty + 8 * i) * 128 + c * 32 + k];
                acc[i][0] = fmaf(xv, w4.x, acc[i][0]);
                acc[i][1] = fmaf(xv, w4.y, acc[i][1]);
                acc[i][2] = fmaf(xv, w4.z, acc[i][2]);
                acc[i][3] = fmaf(xv, w4.w, acc[i][3]);
            }
        }
    }

    float4* O4 = (float4*)O;
#pragma unroll
    for (int i = 0; i < 8; i++) {
        int r = rowBase + ty + 8 * i;
        if (r < nrows)
            O4[(size_t)r * 32 + tx] = make_float4(acc[i][0], acc[i][1], acc[i][2], acc[i][3]);
    }
}

// ---------------- gather-aggregate + self-loop + bias + relu ----------------
// one warp per node; lane handles float4 of features; 4-deep MLP in inner loop.
__global__ __launch_bounds__(256) void k_gather(const float* __restrict__ h,
                                                float* __restrict__ acc,
                                                const int* __restrict__ off,
                                                const int* __restrict__ src,
                                                const float* __restrict__ wgt,
                                                const int* __restrict__ indeg,
                                                const float* __restrict__ bias, int nN) {
    int w = (blockIdx.x * blockDim.x + threadIdx.x) >> 5;
    if (w >= nN) return;
    int lane = threadIdx.x & 31;
    int s = __ldg(&off[w]);
    int e = __ldg(&off[w + 1]);
    const float4* h4 = (const float4*)h;

    // self-loop term: h[w] / deg[w]
    float selfw = 1.0f / (float)(__ldg(&indeg[w]) + 1);
    float4 a = __ldg(&h4[(size_t)w * 32 + lane]);
    a.x *= selfw; a.y *= selfw; a.z *= selfw; a.w *= selfw;
    float4 a2 = make_float4(0.f, 0.f, 0.f, 0.f);
    float4 a3 = make_float4(0.f, 0.f, 0.f, 0.f);
    float4 a4 = make_float4(0.f, 0.f, 0.f, 0.f);

    int j = s;
    for (; j + 3 < e; j += 4) {
        int   r0 = __ldg(&src[j]);     int   r1 = __ldg(&src[j + 1]);
        int   r2 = __ldg(&src[j + 2]); int   r3 = __ldg(&src[j + 3]);
        float w0 = __ldg(&wgt[j]);     float w1 = __ldg(&wgt[j + 1]);
        float w2 = __ldg(&wgt[j + 2]); float w3 = __ldg(&wgt[j + 3]);
        float4 v0 = __ldg(&h4[(size_t)r0 * 32 + lane]);
        float4 v1 = __ldg(&h4[(size_t)r1 * 32 + lane]);
        float4 v2 = __ldg(&h4[(size_t)r2 * 32 + lane]);
        float4 v3 = __ldg(&h4[(size_t)r3 * 32 + lane]);
        a.x  = fmaf(v0.x, w0, a.x);  a.y  = fmaf(v0.y, w0, a.y);
        a.z  = fmaf(v0.z, w0, a.z);  a.w  = fmaf(v0.w, w0, a.w);
        a2.x = fmaf(v1.x, w1, a2.x); a2.y = fmaf(v1.y, w1, a2.y);
        a2.z = fmaf(v1.z, w1, a2.z); a2.w = fmaf(v1.w, w1, a2.w);
        a3.x = fmaf(v2.x, w2, a3.x); a3.y = fmaf(v2.y, w2, a3.y);
        a3.z = fmaf(v2.z, w2, a3.z); a3.w = fmaf(v2.w, w2, a3.w);
        a4.x = fmaf(v3.x, w3, a4.x); a4.y = fmaf(v3.y, w3, a4.y);
        a4.z = fmaf(v3.z, w3, a4.z); a4.w = fmaf(v3.w, w3, a4.w);
    }
    for (; j < e; j++) {
        int   r0 = __ldg(&src[j]);
        float w0 = __ldg(&wgt[j]);
        float4 v0 = __ldg(&h4[(size_t)r0 * 32 + lane]);
        a.x = fmaf(v0.x, w0, a.x); a.y = fmaf(v0.y, w0, a.y);
        a.z = fmaf(v0.z, w0, a.z); a.w = fmaf(v0.w, w0, a.w);
    }
    float4 b = __ldg(&((const float4*)bias)[lane]);
    a.x = fmaxf(a.x + a2.x + a3.x + a4.x + b.x, 0.f);
    a.y = fmaxf(a.y + a2.y + a3.y + a4.y + b.y, 0.f);
    a.z = fmaxf(a.z + a2.z + a3.z + a4.z + b.z, 0.f);
    a.w = fmaxf(a.w + a2.w + a3.w + a4.w + b.w, 0.f);
    ((float4*)acc)[(size_t)w * 32 + lane] = a;
}

// ---------------- segment boundaries from sorted batch ----------------
__global__ void k_bounds(const int* __restrict__ batch, int* __restrict__ gs,
                         int* __restrict__ ge, int n) {
    int i = blockIdx.x * blockDim.x + threadIdx.x;
    if (i >= n) return;
    int b = batch[i];
    if (i == 0 || batch[i - 1] != b) gs[b] = i;
    if (i == n - 1 || batch[i + 1] != b) ge[b] = i + 1;
}

// ---------------- chunked max pool (values >= 0; int atomicMax) ----------------
__global__ __launch_bounds__(128) void k_pool(const float* __restrict__ acc,
                                              const int* __restrict__ gs,
                                              const int* __restrict__ ge,
                                              float* __restrict__ pool) {
    int g = blockIdx.x;
    int chunk = blockIdx.y;
    int f = threadIdx.x;
    int s = gs[g], e = ge[g];
    int len = e - s;
    int per = (len + POOL_CHUNKS - 1) / POOL_CHUNKS;
    int cs = s + chunk * per;
    int ce = min(cs + per, e);
    if (cs >= ce) return;
    float m = 0.0f;
    for (int n = cs; n < ce; n++)
        m = fmaxf(m, acc[(size_t)n * D + f]);
    atomicMax((int*)&pool[g * D + f], __float_as_int(m));
}

// ---------------- head: z0 = relu(pool @ lin0_w + lin0_b) ----------------
__global__ void k_head1(const float* __restrict__ pool, const float* __restrict__ W,
                        const float* __restrict__ b, float* __restrict__ z0) {
    __shared__ float p[128];
    int g = blockIdx.x;
    int j = threadIdx.x;
    p[j] = pool[g * D + j];
    __syncthreads();
    float acc = b[j];
    for (int k = 0; k < 128; k++)
        acc = fmaf(p[k], __ldg(&W[k * 128 + j]), acc);
    z0[g * D + j] = fmaxf(acc, 0.f);
}

// ---------------- head: out = log_softmax(relu(z0 @ lin1_w + lin1_b)) ----------------
__global__ void k_head2(const float* __restrict__ z0, const float* __restrict__ W,
                        const float* __restrict__ b, float* __restrict__ out) {
    __shared__ float z[128];
    int g = blockIdx.x;
    int t = threadIdx.x;
#pragma unroll
    for (int i = 0; i < 4; i++) z[t + 32 * i] = z0[g * D + t + 32 * i];
    __syncwarp();
    float acc = 0.f;
    if (t < N_CLASSES) {
        acc = b[t];
        for (int k = 0; k < 128; k++)
            acc = fmaf(z[k], __ldg(&W[k * N_CLASSES + t]), acc);
        acc = fmaxf(acc, 0.f);
    }
    float vmax = (t < N_CLASSES) ? acc : -3.402823466e38f;
#pragma unroll
    for (int o = 16; o > 0; o >>= 1)
        vmax = fmaxf(vmax, __shfl_xor_sync(0xffffffff, vmax, o));
    float e = (t < N_CLASSES) ? expf(acc - vmax) : 0.f;
    float s = e;
#pragma unroll
    for (int o = 16; o > 0; o >>= 1)
        s += __shfl_xor_sync(0xffffffff, s, o);
    if (t < N_CLASSES)
        out[g * N_CLASSES + t] = acc - vmax - logf(s);
}

// ---------------- launch ----------------
extern "C" void kernel_launch(void* const* d_in, const int* in_sizes, int n_in,
                              void* d_out, int out_size) {
    const float* x = 0; const int* ei = 0; const int* batch = 0;
    const float* w16k[3] = {0,0,0}; int nw = 0;
    const float* b128[3] = {0,0,0}; int nb = 0;
    const float* lin1_w = 0; const float* lin1_b = 0;
    for (int i = 0; i < n_in; i++) {
        int s = in_sizes[i];
        if      (s == N_NODES * D)      x      = (const float*)d_in[i];
        else if (s == 2 * N_EDGES)      ei     = (const int*)  d_in[i];
        else if (s == N_NODES)          batch  = (const int*)  d_in[i];
        else if (s == D * D)            { if (nw < 3) w16k[nw++] = (const float*)d_in[i]; }
        else if (s == D)                { if (nb < 3) b128[nb++] = (const float*)d_in[i]; }
        else if (s == D * N_CLASSES)    lin1_w = (const float*)d_in[i];
        else if (s == N_CLASSES)        lin1_b = (const float*)d_in[i];
    }
    const float* conv0_w = w16k[0];
    const float* conv1_w = w16k[1];
    const float* lin0_w  = w16k[2];
    const float* conv0_b = b128[0];
    const float* conv1_b = b128[1];
    const float* lin0_b  = b128[2];
    float* out = (float*)d_out;

    // Runtime addresses for ALL scratch (symbol addressing in device code broken here).
    static float* p_h = 0; static float* p_acc = 0; static int* p_ind = 0;
    static float* p_dinv = 0; static int* p_off = 0; static int* p_cur = 0;
    static int* p_src = 0; static float* p_wgt = 0; static int* p_part = 0;
    static float* p_pool = 0; static float* p_z0 = 0;
    static int* p_gs = 0; static int* p_ge = 0;
    if (!p_h) {
        cudaGetSymbolAddress((void**)&p_h,    g_hx);
        cudaGetSymbolAddress((void**)&p_acc,  g_accx);
        cudaGetSymbolAddress((void**)&p_ind,  g_indeg);
        cudaGetSymbolAddress((void**)&p_dinv, g_dinvx);
        cudaGetSymbolAddress((void**)&p_off,  g_offx);
        cudaGetSymbolAddress((void**)&p_cur,  g_curx);
        cudaGetSymbolAddress((void**)&p_src,  g_srcx);
        cudaGetSymbolAddress((void**)&p_wgt,  g_wgtx);
        cudaGetSymbolAddress((void**)&p_part, g_partx);
        cudaGetSymbolAddress((void**)&p_pool, g_poolx);
        cudaGetSymbolAddress((void**)&p_z0,   g_z0x);
        cudaGetSymbolAddress((void**)&p_gs,   g_startx);
        cudaGetSymbolAddress((void**)&p_ge,   g_endx);
    }

    const int T = 256;
    const int gemm_blocks = (N_NODES + 63) / 64;
    const int gath_blocks = (N_NODES * 32 + T - 1) / T;

    // CSR build (parallel scan)
    k_seed    <<<(N_NODES + T - 1) / T, T>>>(p_ind, p_cur, p_pool, N_NODES);
    k_count   <<<(N_EDGES + T - 1) / T, T>>>(ei, p_ind, N_EDGES);
    k_dinv    <<<(N_NODES + T - 1) / T, T>>>(p_ind, p_dinv, N_NODES);
    k_part    <<<SCAN_NBLK, SCAN_B>>>(p_ind, p_part, N_NODES);
    k_scanpart<<<1, SCAN_B>>>(p_part, p_off, SCAN_NBLK, N_NODES);
    k_off     <<<SCAN_NBLK, SCAN_B>>>(p_ind, p_part, p_off, N_NODES);
    k_fill    <<<(N_EDGES + T - 1) / T, T>>>(ei, p_off, p_cur, p_src, p_wgt, p_dinv, N_EDGES);
    k_bounds  <<<(N_NODES + T - 1) / T, T>>>(batch, p_gs, p_ge, N_NODES);

    // conv0: h = x@w0 ; acc = relu(agg(h) + b0)
    k_gemm  <<<gemm_blocks, T>>>(x, conv0_w, p_h, N_NODES);
    k_gather<<<gath_blocks, T>>>(p_h, p_acc, p_off, p_src, p_wgt, p_ind, conv0_b, N_NODES);

    // conv1
    k_gemm  <<<gemm_blocks, T>>>(p_acc, conv1_w, p_h, N_NODES);
    k_gather<<<gath_blocks, T>>>(p_h, p_acc, p_off, p_src, p_wgt, p_ind, conv1_b, N_NODES);

    // pool + head
    dim3 pg(N_GRAPHS, POOL_CHUNKS);
    k_pool<<<pg, 128>>>(p_acc, p_gs, p_ge, p_pool);
    k_head1<<<N_GRAPHS, 128>>>(p_pool, lin0_w, lin0_b, p_z0);
    k_head2<<<N_GRAPHS, 32>>>(p_z0, lin1_w, lin1_b, out);
}

// round 12
// speedup vs baseline: 9.5190x; 1.0076x over previous
#include <cuda_runtime.h>
#include <cuda_bf16.h>
#include <math.h>
#include <mma.h>

using namespace nvcuda;

#define N_NODES   50000
#define N_EDGES   800000
#define D         128
#define N_GRAPHS  64
#define N_CLASSES 10
#define POOL_CHUNKS 16
#define SCAN_B 256
#define SCAN_NBLK ((N_NODES + SCAN_B - 1) / SCAN_B)   // 196
#define LDSP 132                                      // padded smem row (floats)

// ---------------- scratch (accessed ONLY via runtime pointers passed as params;
//                  symbol-relative addressing of big arrays proven broken here) ------
__device__ __align__(16) float g_hx  [N_NODES * D + 1024];
__device__ __align__(16) float g_accx[N_NODES * D + 1024];
__device__ __align__(16) int   g_indeg[N_NODES + 256];
__device__ __align__(16) float g_dinvx[N_NODES + 256];
__device__ __align__(16) int   g_offx [N_NODES + 256];     // CSR offsets (N+1 used)
__device__ __align__(16) int   g_curx [N_NODES + 256];     // fill cursors
__device__ __align__(16) int   g_srcx [N_EDGES + 256];     // CSR source ids
__device__ __align__(16) float g_wgtx [N_EDGES + 256];     // CSR edge weights
__device__ __align__(16) int   g_partx[SCAN_NBLK + 8];     // block partial sums
__device__ __align__(16) float g_poolx[N_GRAPHS * D];
__device__ __align__(16) float g_z0x  [N_GRAPHS * D];
__device__ __align__(16) int   g_startx[N_GRAPHS];
__device__ __align__(16) int   g_endx  [N_GRAPHS];

// ---------------- init: indeg=0, cursors=0, pool=0 ----------------
__global__ void k_seed(int* __restrict__ indeg, int* __restrict__ cur,
                       float* __restrict__ pool, int n) {
    int i = blockIdx.x * blockDim.x + threadIdx.x;
    if (i < n) { indeg[i] = 0; cur[i] = 0; }
    if (i < N_GRAPHS * D) pool[i] = 0.0f;   // identity for max of relu'd (>=0) values
}

__global__ void k_count(const int* __restrict__ ei, int* __restrict__ indeg, int nE) {
    int e = blockIdx.x * blockDim.x + threadIdx.x;
    if (e < nE) atomicAdd(&indeg[ei[nE + e]], 1);   // planar (2,E): dst = ei[E+e]
}

__global__ void k_dinv(const int* __restrict__ indeg, float* __restrict__ dinv, int n) {
    int i = blockIdx.x * blockDim.x + threadIdx.x;
    if (i < n) dinv[i] = rsqrtf((float)(indeg[i] + 1));
}

// ---------------- scan phase 1: per-block sums ----------------
__global__ __launch_bounds__(SCAN_B) void k_part(const int* __restrict__ indeg,
                                                 int* __restrict__ part, int n) {
    __shared__ int sh[SCAN_B];
    int t = threadIdx.x;
    int i = blockIdx.x * SCAN_B + t;
    sh[t] = (i < n) ? indeg[i] : 0;
    __syncthreads();
#pragma unroll
    for (int o = SCAN_B / 2; o > 0; o >>= 1) {
        if (t < o) sh[t] += sh[t + o];
        __syncthreads();
    }
    if (t == 0) part[blockIdx.x] = sh[0];
}

// ---------------- scan phase 2: inclusive scan of partials (1 small block) ----------
__global__ __launch_bounds__(SCAN_B) void k_scanpart(int* __restrict__ part,
                                                     int* __restrict__ off, int nblk, int n) {
    __shared__ int sh[SCAN_B];
    int t = threadIdx.x;
    sh[t] = (t < nblk) ? part[t] : 0;
    __syncthreads();
#pragma unroll
    for (int o = 1; o < SCAN_B; o <<= 1) {
        int v = (t >= o) ? sh[t - o] : 0;
        __syncthreads();
        sh[t] += v;
        __syncthreads();
    }
    if (t < nblk) part[t] = sh[t];          // inclusive sums
    if (t == 0) off[n] = N_EDGES;           // total edges (constant)
}

// ---------------- scan phase 3: in-block exclusive scan + base -> offsets -----------
__global__ __launch_bounds__(SCAN_B) void k_off(const int* __restrict__ indeg,
                                                const int* __restrict__ part,
                                                int* __restrict__ off, int n) {
    __shared__ int sh[SCAN_B];
    int t = threadIdx.x;
    int b = blockIdx.x;
    int i = b * SCAN_B + t;
    int v = (i < n) ? indeg[i] : 0;
    sh[t] = v;
    __syncthreads();
#pragma unroll
    for (int o = 1; o < SCAN_B; o <<= 1) {   // inclusive Hillis-Steele
        int u = (t >= o) ? sh[t - o] : 0;
        __syncthreads();
        sh[t] += u;
        __syncthreads();
    }
    int base = (b == 0) ? 0 : part[b - 1];
    if (i < n) off[i] = base + sh[t] - v;    // exclusive
}

// ---------------- CSR fill: src ids + edge weights ----------------
__global__ void k_fill(const int* __restrict__ ei, const int* __restrict__ off,
                       int* __restrict__ cur, int* __restrict__ src,
                       float* __restrict__ wgt, const float* __restrict__ dinv, int nE) {
    int e = blockIdx.x * blockDim.x + threadIdx.x;
    if (e >= nE) return;
    int r = ei[e];
    int c = ei[nE + e];
    int pos = atomicAdd(&cur[c], 1);
    int j = off[c] + pos;
    src[j] = r;
    wgt[j] = dinv[r] * dinv[c];
}

// ---------------- TF32 tensor-core GEMM: O[n,128] = A[n,128] @ W[128,128] -----------
// 64-row tile per block, 256 threads (8 warps: 4 row-strips x 2 col-halves).
__global__ __launch_bounds__(256) void k_gemm_tc(const float* __restrict__ A,
                                                 const float* __restrict__ W,
                                                 float* __restrict__ O, int nrows) {
    extern __shared__ float sm[];
    float* sA = sm;                    // 64 x LDSP
    float* sW = sm + 64 * LDSP;        // 128 x LDSP
    const int tid = threadIdx.x;
    const int rowBase = blockIdx.x * 64;
    const float4* A4 = (const float4*)A;
    const float4* W4 = (const float4*)W;

    // load A tile (64x128) with row guard
#pragma unroll
    for (int i = 0; i < 8; i++) {
        int idx = tid + 256 * i;       // 0..2047
        int r = idx >> 5;
        int c4 = idx & 31;
        float4 v = (rowBase + r < nrows) ? A4[(size_t)(rowBase + r) * 32 + c4]
                                         : make_float4(0.f, 0.f, 0.f, 0.f);
        *(float4*)&sA[r * LDSP + c4 * 4] = v;
    }
    // load W (128x128)
#pragma unroll
    for (int i = 0; i < 16; i++) {
        int idx = tid + 256 * i;       // 0..4095
        int r = idx >> 5;
        int c4 = idx & 31;
        *(float4*)&sW[r * LDSP + c4 * 4] = W4[idx];
    }
    __syncthreads();

    const int warpId = tid >> 5;
    const int wr = warpId & 3;         // 16-row strip
    const int wc = warpId >> 2;        // 64-col half

    wmma::fragment<wmma::accumulator, 16, 16, 8, float> c[4];
#pragma unroll
    for (int j = 0; j < 4; j++) wmma::fill_fragment(c[j], 0.0f);

#pragma unroll
    for (int k = 0; k < 16; k++) {
        wmma::fragment<wmma::matrix_a, 16, 16, 8, wmma::precision::tf32, wmma::row_major> a;
        wmma::load_matrix_sync(a, &sA[wr * 16 * LDSP + k * 8], LDSP);
#pragma unroll
        for (int i = 0; i < a.num_elements; i++) a.x[i] = wmma::__float_to_tf32(a.x[i]);
#pragma unroll
        for (int j = 0; j < 4; j++) {
            wmma::fragment<wmma::matrix_b, 16, 16, 8, wmma::precision::tf32, wmma::row_major> b;
            wmma::load_matrix_sync(b, &sW[k * 8 * LDSP + wc * 64 + j * 16], LDSP);
#pragma unroll
            for (int i = 0; i < b.num_elements; i++) b.x[i] = wmma::__float_to_tf32(b.x[i]);
            wmma::mma_sync(c[j], a, b, c[j]);
        }
    }

    // stage C into sA, then guarded vector stores
    __syncthreads();
#pragma unroll
    for (int j = 0; j < 4; j++)
        wmma::store_matrix_sync(&sA[wr * 16 * LDSP + wc * 64 + j * 16], c[j], LDSP,
                                wmma::mem_row_major);
    __syncthreads();
    float4* O4 = (float4*)O;
#pragma unroll
    for (int i = 0; i < 8; i++) {
        int idx = tid + 256 * i;
        int r = idx >> 5;
        int c4 = idx & 31;
        if (rowBase + r < nrows)
            O4[(size_t)(rowBase + r) * 32 + c4] = *(float4*)&sA[r * LDSP + c4 * 4];
    }
}

// ---------------- gather-aggregate + self-loop + bias + relu ----------------
__global__ __launch_bounds__(256) void k_gather(const float* __restrict__ h,
                                                float* __restrict__ acc,
                                                const int* __restrict__ off,
                                                const int* __restrict__ src,
                                                const float* __restrict__ wgt,
                                                const int* __restrict__ indeg,
                                                const float* __restrict__ bias, int nN) {
    int w = (blockIdx.x * blockDim.x + threadIdx.x) >> 5;
    if (w >= nN) return;
    int lane = threadIdx.x & 31;
    int s = __ldg(&off[w]);
    int e = __ldg(&off[w + 1]);
    const float4* h4 = (const float4*)h;

    float selfw = 1.0f / (float)(__ldg(&indeg[w]) + 1);
    float4 a = __ldg(&h4[(size_t)w * 32 + lane]);
    a.x *= selfw; a.y *= selfw; a.z *= selfw; a.w *= selfw;
    float4 a2 = make_float4(0.f, 0.f, 0.f, 0.f);
    float4 a3 = make_float4(0.f, 0.f, 0.f, 0.f);
    float4 a4 = make_float4(0.f, 0.f, 0.f, 0.f);

    int j = s;
    for (; j + 3 < e; j += 4) {
        int   r0 = __ldg(&src[j]);     int   r1 = __ldg(&src[j + 1]);
        int   r2 = __ldg(&src[j + 2]); int   r3 = __ldg(&src[j + 3]);
        float w0 = __ldg(&wgt[j]);     float w1 = __ldg(&wgt[j + 1]);
        float w2 = __ldg(&wgt[j + 2]); float w3 = __ldg(&wgt[j + 3]);
        float4 v0 = __ldg(&h4[(size_t)r0 * 32 + lane]);
        float4 v1 = __ldg(&h4[(size_t)r1 * 32 + lane]);
        float4 v2 = __ldg(&h4[(size_t)r2 * 32 + lane]);
        float4 v3 = __ldg(&h4[(size_t)r3 * 32 + lane]);
        a.x  = fmaf(v0.x, w0, a.x);  a.y  = fmaf(v0.y, w0, a.y);
        a.z  = fmaf(v0.z, w0, a.z);  a.w  = fmaf(v0.w, w0, a.w);
        a2.x = fmaf(v1.x, w1, a2.x); a2.y = fmaf(v1.y, w1, a2.y);
        a2.z = fmaf(v1.z, w1, a2.z); a2.w = fmaf(v1.w, w1, a2.w);
        a3.x = fmaf(v2.x, w2, a3.x); a3.y = fmaf(v2.y, w2, a3.y);
        a3.z = fmaf(v2.z, w2, a3.z); a3.w = fmaf(v2.w, w2, a3.w);
        a4.x = fmaf(v3.x, w3, a4.x); a4.y = fmaf(v3.y, w3, a4.y);
        a4.z = fmaf(v3.z, w3, a4.z); a4.w = fmaf(v3.w, w3, a4.w);
    }
    for (; j < e; j++) {
        int   r0 = __ldg(&src[j]);
        float w0 = __ldg(&wgt[j]);
        float4 v0 = __ldg(&h4[(size_t)r0 * 32 + lane]);
        a.x = fmaf(v0.x, w0, a.x); a.y = fmaf(v0.y, w0, a.y);
        a.z = fmaf(v0.z, w0, a.z); a.w = fmaf(v0.w, w0, a.w);
    }
    float4 b = __ldg(&((const float4*)bias)[lane]);
    a.x = fmaxf(a.x + a2.x + a3.x + a4.x + b.x, 0.f);
    a.y = fmaxf(a.y + a2.y + a3.y + a4.y + b.y, 0.f);
    a.z = fmaxf(a.z + a2.z + a3.z + a4.z + b.z, 0.f);
    a.w = fmaxf(a.w + a2.w + a3.w + a4.w + b.w, 0.f);
    ((float4*)acc)[(size_t)w * 32 + lane] = a;
}

// ---------------- segment boundaries from sorted batch ----------------
__global__ void k_bounds(const int* __restrict__ batch, int* __restrict__ gs,
                         int* __restrict__ ge, int n) {
    int i = blockIdx.x * blockDim.x + threadIdx.x;
    if (i >= n) return;
    int b = batch[i];
    if (i == 0 || batch[i - 1] != b) gs[b] = i;
    if (i == n - 1 || batch[i + 1] != b) ge[b] = i + 1;
}

// ---------------- chunked max pool (values >= 0; int atomicMax) ----------------
__global__ __launch_bounds__(128) void k_pool(const float* __restrict__ acc,
                                              const int* __restrict__ gs,
                                              const int* __restrict__ ge,
                                              float* __restrict__ pool) {
    int g = blockIdx.x;
    int chunk = blockIdx.y;
    int f = threadIdx.x;
    int s = gs[g], e = ge[g];
    int len = e - s;
    int per = (len + POOL_CHUNKS - 1) / POOL_CHUNKS;
    int cs = s + chunk * per;
    int ce = min(cs + per, e);
    if (cs >= ce) return;
    float m = 0.0f;
    for (int n = cs; n < ce; n++)
        m = fmaxf(m, acc[(size_t)n * D + f]);
    atomicMax((int*)&pool[g * D + f], __float_as_int(m));
}

// ---------------- head: z0 = relu(pool @ lin0_w + lin0_b) ----------------
__global__ void k_head1(const float* __restrict__ pool, const float* __restrict__ W,
                        const float* __restrict__ b, float* __restrict__ z0) {
    __shared__ float p[128];
    int g = blockIdx.x;
    int j = threadIdx.x;
    p[j] = pool[g * D + j];
    __syncthreads();
    float acc = b[j];
    for (int k = 0; k < 128; k++)
        acc = fmaf(p[k], __ldg(&W[k * 128 + j]), acc);
    z0[g * D + j] = fmaxf(acc, 0.f);
}

// ---------------- head: out = log_softmax(relu(z0 @ lin1_w + lin1_b)) ----------------
__global__ void k_head2(const float* __restrict__ z0, const float* __restrict__ W,
                        const float* __restrict__ b, float* __restrict__ out) {
    __shared__ float z[128];
    int g = blockIdx.x;
    int t = threadIdx.x;
#pragma unroll
    for (int i = 0; i < 4; i++) z[t + 32 * i] = z0[g * D + t + 32 * i];
    __syncwarp();
    float acc = 0.f;
    if (t < N_CLASSES) {
        acc = b[t];
        for (int k = 0; k < 128; k++)
            acc = fmaf(z[k], __ldg(&W[k * N_CLASSES + t]), acc);
        acc = fmaxf(acc, 0.f);
    }
    float vmax = (t < N_CLASSES) ? acc : -3.402823466e38f;
#pragma unroll
    for (int o = 16; o > 0; o >>= 1)
        vmax = fmaxf(vmax, __shfl_xor_sync(0xffffffff, vmax, o));
    float e = (t < N_CLASSES) ? expf(acc - vmax) : 0.f;
    float s = e;
#pragma unroll
    for (int o = 16; o > 0; o >>= 1)
        s += __shfl_xor_sync(0xffffffff, s, o);
    if (t < N_CLASSES)
        out[g * N_CLASSES + t] = acc - vmax - logf(s);
}

// ---------------- launch ----------------
extern "C" void kernel_launch(void* const* d_in, const int* in_sizes, int n_in,
                              void* d_out, int out_size) {
    const float* x = 0; const int* ei = 0; const int* batch = 0;
    const float* w16k[3] = {0,0,0}; int nw = 0;
    const float* b128[3] = {0,0,0}; int nb = 0;
    const float* lin1_w = 0; const float* lin1_b = 0;
    for (int i = 0; i < n_in; i++) {
        int s = in_sizes[i];
        if      (s == N_NODES * D)      x      = (const float*)d_in[i];
        else if (s == 2 * N_EDGES)      ei     = (const int*)  d_in[i];
        else if (s == N_NODES)          batch  = (const int*)  d_in[i];
        else if (s == D * D)            { if (nw < 3) w16k[nw++] = (const float*)d_in[i]; }
        else if (s == D)                { if (nb < 3) b128[nb++] = (const float*)d_in[i]; }
        else if (s == D * N_CLASSES)    lin1_w = (const float*)d_in[i];
        else if (s == N_CLASSES)        lin1_b = (const float*)d_in[i];
    }
    const float* conv0_w = w16k[0];
    const float* conv1_w = w16k[1];
    const float* lin0_w  = w16k[2];
    const float* conv0_b = b128[0];
    const float* conv1_b = b128[1];
    const float* lin0_b  = b128[2];
    float* out = (float*)d_out;

    // Runtime addresses for ALL scratch (symbol addressing in device code broken here).
    static float* p_h = 0; static float* p_acc = 0; static int* p_ind = 0;
    static float* p_dinv = 0; static int* p_off = 0; static int* p_cur = 0;
    static int* p_src = 0; static float* p_wgt = 0; static int* p_part = 0;
    static float* p_pool = 0; static float* p_z0 = 0;
    static int* p_gs = 0; static int* p_ge = 0;
    static int gemm_smem = (64 + 128) * LDSP * 4;
    if (!p_h) {
        cudaGetSymbolAddress((void**)&p_h,    g_hx);
        cudaGetSymbolAddress((void**)&p_acc,  g_accx);
        cudaGetSymbolAddress((void**)&p_ind,  g_indeg);
        cudaGetSymbolAddress((void**)&p_dinv, g_dinvx);
        cudaGetSymbolAddress((void**)&p_off,  g_offx);
        cudaGetSymbolAddress((void**)&p_cur,  g_curx);
        cudaGetSymbolAddress((void**)&p_src,  g_srcx);
        cudaGetSymbolAddress((void**)&p_wgt,  g_wgtx);
        cudaGetSymbolAddress((void**)&p_part, g_partx);
        cudaGetSymbolAddress((void**)&p_pool, g_poolx);
        cudaGetSymbolAddress((void**)&p_z0,   g_z0x);
        cudaGetSymbolAddress((void**)&p_gs,   g_startx);
        cudaGetSymbolAddress((void**)&p_ge,   g_endx);
        cudaFuncSetAttribute(k_gemm_tc, cudaFuncAttributeMaxDynamicSharedMemorySize,
                             gemm_smem);
    }

    const int T = 256;
    const int gemm_blocks = (N_NODES + 63) / 64;
    const int gath_blocks = (N_NODES * 32 + T - 1) / T;

    // CSR build (parallel scan)
    k_seed    <<<(N_NODES + T - 1) / T, T>>>(p_ind, p_cur, p_pool, N_NODES);
    k_count   <<<(N_EDGES + T - 1) / T, T>>>(ei, p_ind, N_EDGES);
    k_dinv    <<<(N_NODES + T - 1) / T, T>>>(p_ind, p_dinv, N_NODES);
    k_part    <<<SCAN_NBLK, SCAN_B>>>(p_ind, p_part, N_NODES);
    k_scanpart<<<1, SCAN_B>>>(p_part, p_off, SCAN_NBLK, N_NODES);
    k_off     <<<SCAN_NBLK, SCAN_B>>>(p_ind, p_part, p_off, N_NODES);
    k_fill    <<<(N_EDGES + T - 1) / T, T>>>(ei, p_off, p_cur, p_src, p_wgt, p_dinv, N_EDGES);
    k_bounds  <<<(N_NODES + T - 1) / T, T>>>(batch, p_gs, p_ge, N_NODES);

    // conv0: h = x@w0 ; acc = relu(agg(h) + b0)
    k_gemm_tc<<<gemm_blocks, T, gemm_smem>>>(x, conv0_w, p_h, N_NODES);
    k_gather <<<gath_blocks, T>>>(p_h, p_acc, p_off, p_src, p_wgt, p_ind, conv0_b, N_NODES);

    // conv1
    k_gemm_tc<<<gemm_blocks, T, gemm_smem>>>(p_acc, conv1_w, p_h, N_NODES);
    k_gather <<<gath_blocks, T>>>(p_h, p_acc, p_off, p_src, p_wgt, p_ind, conv1_b, N_NODES);

    // pool + head
    dim3 pg(N_GRAPHS, POOL_CHUNKS);
    k_pool<<<pg, 128>>>(p_acc, p_gs, p_ge, p_pool);
    k_head1<<<N_GRAPHS, 128>>>(p_pool, lin0_w, lin0_b, p_z0);
    k_head2<<<N_GRAPHS, 32>>>(p_z0, lin1_w, lin1_b, out);
}

// round 13
// speedup vs baseline: 10.3354x; 1.0858x over previous
#include <cuda_runtime.h>
#include <cuda_bf16.h>
#include <math.h>
#include <mma.h>

using namespace nvcuda;

#define N_NODES   50000
#define N_EDGES   800000
#define D         128
#define N_GRAPHS  64
#define N_CLASSES 10
#define POOL_CHUNKS 16
#define SCAN_B 256
#define SCAN_NBLK ((N_NODES + SCAN_B - 1) / SCAN_B)   // 196
#define LDSP 132                                      // padded smem row (floats)

// ---------------- scratch (accessed ONLY via runtime pointers passed as params;
//                  symbol-relative addressing of big arrays proven broken here) ------
__device__ __align__(16) __nv_bfloat162 g_hb[N_NODES * 64 + 1024];  // h in bf16 pairs
__device__ __align__(16) float g_accx[N_NODES * D + 1024];
__device__ __align__(16) int   g_indeg[N_NODES + 256];
__device__ __align__(16) float g_dinvx[N_NODES + 256];
__device__ __align__(16) int   g_offx [N_NODES + 256];     // CSR offsets (N+1 used)
__device__ __align__(16) int   g_curx [N_NODES + 256];     // fill cursors
__device__ __align__(16) int   g_srcx [N_EDGES + 256];     // CSR source ids
__device__ __align__(16) float g_wgtx [N_EDGES + 256];     // CSR edge weights
__device__ __align__(16) int   g_partx[SCAN_NBLK + 8];     // block partial sums
__device__ __align__(16) float g_poolx[N_GRAPHS * D];
__device__ __align__(16) float g_z0x  [N_GRAPHS * D];
__device__ __align__(16) int   g_startx[N_GRAPHS];
__device__ __align__(16) int   g_endx  [N_GRAPHS];

// ---------------- init: indeg=0, cursors=0, pool=0 ----------------
__global__ void k_seed(int* __restrict__ indeg, int* __restrict__ cur,
                       float* __restrict__ pool, int n) {
    int i = blockIdx.x * blockDim.x + threadIdx.x;
    if (i < n) { indeg[i] = 0; cur[i] = 0; }
    if (i < N_GRAPHS * D) pool[i] = 0.0f;   // identity for max of relu'd (>=0) values
}

__global__ void k_count(const int* __restrict__ ei, int* __restrict__ indeg, int nE) {
    int e = blockIdx.x * blockDim.x + threadIdx.x;
    if (e < nE) atomicAdd(&indeg[ei[nE + e]], 1);   // planar (2,E): dst = ei[E+e]
}

__global__ void k_dinv(const int* __restrict__ indeg, float* __restrict__ dinv, int n) {
    int i = blockIdx.x * blockDim.x + threadIdx.x;
    if (i < n) dinv[i] = rsqrtf((float)(indeg[i] + 1));
}

// ---------------- scan phase 1: per-block sums ----------------
__global__ __launch_bounds__(SCAN_B) void k_part(const int* __restrict__ indeg,
                                                 int* __restrict__ part, int n) {
    __shared__ int sh[SCAN_B];
    int t = threadIdx.x;
    int i = blockIdx.x * SCAN_B + t;
    sh[t] = (i < n) ? indeg[i] : 0;
    __syncthreads();
#pragma unroll
    for (int o = SCAN_B / 2; o > 0; o >>= 1) {
        if (t < o) sh[t] += sh[t + o];
        __syncthreads();
    }
    if (t == 0) part[blockIdx.x] = sh[0];
}

// ---------------- scan phase 2: inclusive scan of partials (1 small block) ----------
__global__ __launch_bounds__(SCAN_B) void k_scanpart(int* __restrict__ part,
                                                     int* __restrict__ off, int nblk, int n) {
    __shared__ int sh[SCAN_B];
    int t = threadIdx.x;
    sh[t] = (t < nblk) ? part[t] : 0;
    __syncthreads();
#pragma unroll
    for (int o = 1; o < SCAN_B; o <<= 1) {
        int v = (t >= o) ? sh[t - o] : 0;
        __syncthreads();
        sh[t] += v;
        __syncthreads();
    }
    if (t < nblk) part[t] = sh[t];          // inclusive sums
    if (t == 0) off[n] = N_EDGES;           // total edges (constant)
}

// ---------------- scan phase 3: in-block exclusive scan + base -> offsets -----------
__global__ __launch_bounds__(SCAN_B) void k_off(const int* __restrict__ indeg,
                                                const int* __restrict__ part,
                                                int* __restrict__ off, int n) {
    __shared__ int sh[SCAN_B];
    int t = threadIdx.x;
    int b = blockIdx.x;
    int i = b * SCAN_B + t;
    int v = (i < n) ? indeg[i] : 0;
    sh[t] = v;
    __syncthreads();
#pragma unroll
    for (int o = 1; o < SCAN_B; o <<= 1) {   // inclusive Hillis-Steele
        int u = (t >= o) ? sh[t - o] : 0;
        __syncthreads();
        sh[t] += u;
        __syncthreads();
    }
    int base = (b == 0) ? 0 : part[b - 1];
    if (i < n) off[i] = base + sh[t] - v;    // exclusive
}

// ---------------- CSR fill: src ids + edge weights ----------------
__global__ void k_fill(const int* __restrict__ ei, const int* __restrict__ off,
                       int* __restrict__ cur, int* __restrict__ src,
                       float* __restrict__ wgt, const float* __restrict__ dinv, int nE) {
    int e = blockIdx.x * blockDim.x + threadIdx.x;
    if (e >= nE) return;
    int r = ei[e];
    int c = ei[nE + e];
    int pos = atomicAdd(&cur[c], 1);
    int j = off[c] + pos;
    src[j] = r;
    wgt[j] = dinv[r] * dinv[c];
}

// ---------------- TF32 tensor-core GEMM: Hb[n,128](bf16) = A[n,128] @ W[128,128] ----
// 64-row tile per block, 256 threads (8 warps: 4 row-strips x 2 col-halves).
__global__ __launch_bounds__(256) void k_gemm_tc(const float* __restrict__ A,
                                                 const float* __restrict__ W,
                                                 __nv_bfloat162* __restrict__ HB, int nrows) {
    extern __shared__ float sm[];
    float* sA = sm;                    // 64 x LDSP
    float* sW = sm + 64 * LDSP;        // 128 x LDSP
    const int tid = threadIdx.x;
    const int rowBase = blockIdx.x * 64;
    const float4* A4 = (const float4*)A;
    const float4* W4 = (const float4*)W;

    // load A tile (64x128) with row guard
#pragma unroll
    for (int i = 0; i < 8; i++) {
        int idx = tid + 256 * i;       // 0..2047
        int r = idx >> 5;
        int c4 = idx & 31;
        float4 v = (rowBase + r < nrows) ? A4[(size_t)(rowBase + r) * 32 + c4]
                                         : make_float4(0.f, 0.f, 0.f, 0.f);
        *(float4*)&sA[r * LDSP + c4 * 4] = v;
    }
    // load W (128x128)
#pragma unroll
    for (int i = 0; i < 16; i++) {
        int idx = tid + 256 * i;       // 0..4095
        int r = idx >> 5;
        int c4 = idx & 31;
        *(float4*)&sW[r * LDSP + c4 * 4] = W4[idx];
    }
    __syncthreads();

    const int warpId = tid >> 5;
    const int wr = warpId & 3;         // 16-row strip
    const int wc = warpId >> 2;        // 64-col half

    wmma::fragment<wmma::accumulator, 16, 16, 8, float> c[4];
#pragma unroll
    for (int j = 0; j < 4; j++) wmma::fill_fragment(c[j], 0.0f);

#pragma unroll
    for (int k = 0; k < 16; k++) {
        wmma::fragment<wmma::matrix_a, 16, 16, 8, wmma::precision::tf32, wmma::row_major> a;
        wmma::load_matrix_sync(a, &sA[wr * 16 * LDSP + k * 8], LDSP);
#pragma unroll
        for (int i = 0; i < a.num_elements; i++) a.x[i] = wmma::__float_to_tf32(a.x[i]);
#pragma unroll
        for (int j = 0; j < 4; j++) {
            wmma::fragment<wmma::matrix_b, 16, 16, 8, wmma::precision::tf32, wmma::row_major> b;
            wmma::load_matrix_sync(b, &sW[k * 8 * LDSP + wc * 64 + j * 16], LDSP);
#pragma unroll
            for (int i = 0; i < b.num_elements; i++) b.x[i] = wmma::__float_to_tf32(b.x[i]);
            wmma::mma_sync(c[j], a, b, c[j]);
        }
    }

    // stage C into sA, then guarded bf16 stores
    __syncthreads();
#pragma unroll
    for (int j = 0; j < 4; j++)
        wmma::store_matrix_sync(&sA[wr * 16 * LDSP + wc * 64 + j * 16], c[j], LDSP,
                                wmma::mem_row_major);
    __syncthreads();
#pragma unroll
    for (int i = 0; i < 8; i++) {
        int idx = tid + 256 * i;
        int r = idx >> 5;
        int c4 = idx & 31;
        if (rowBase + r < nrows) {
            float4 v = *(float4*)&sA[r * LDSP + c4 * 4];
            __nv_bfloat162 lo = __floats2bfloat162_rn(v.x, v.y);
            __nv_bfloat162 hi = __floats2bfloat162_rn(v.z, v.w);
            uint2 u;
            u.x = *(unsigned*)&lo;
            u.y = *(unsigned*)&hi;
            ((uint2*)HB)[(size_t)(rowBase + r) * 32 + c4] = u;
        }
    }
}

// ---------------- gather-aggregate + self-loop + bias + relu (bf16 h) ----------------
// one warp per node; lane handles 4 features (one uint2 = 2 bf162); fp32 accumulate.
__device__ __forceinline__ void bf2acc(uint2 u, float wgt, float4& a) {
    __nv_bfloat162 lo = *(__nv_bfloat162*)&u.x;
    __nv_bfloat162 hi = *(__nv_bfloat162*)&u.y;
    float2 f0 = __bfloat1622float2(lo);
    float2 f1 = __bfloat1622float2(hi);
    a.x = fmaf(f0.x, wgt, a.x); a.y = fmaf(f0.y, wgt, a.y);
    a.z = fmaf(f1.x, wgt, a.z); a.w = fmaf(f1.y, wgt, a.w);
}

__global__ __launch_bounds__(256) void k_gather(const __nv_bfloat162* __restrict__ HB,
                                                float* __restrict__ acc,
                                                const int* __restrict__ off,
                                                const int* __restrict__ src,
                                                const float* __restrict__ wgt,
                                                const int* __restrict__ indeg,
                                                const float* __restrict__ bias, int nN) {
    int w = (blockIdx.x * blockDim.x + threadIdx.x) >> 5;
    if (w >= nN) return;
    int lane = threadIdx.x & 31;
    int s = __ldg(&off[w]);
    int e = __ldg(&off[w + 1]);
    const uint2* hb = (const uint2*)HB;

    // self-loop term: h[w] / deg[w]
    float selfw = 1.0f / (float)(__ldg(&indeg[w]) + 1);
    float4 a = make_float4(0.f, 0.f, 0.f, 0.f);
    bf2acc(__ldg(&hb[(size_t)w * 32 + lane]), selfw, a);
    float4 a2 = make_float4(0.f, 0.f, 0.f, 0.f);
    float4 a3 = make_float4(0.f, 0.f, 0.f, 0.f);
    float4 a4 = make_float4(0.f, 0.f, 0.f, 0.f);

    int j = s;
    for (; j + 3 < e; j += 4) {
        int   r0 = __ldg(&src[j]);     int   r1 = __ldg(&src[j + 1]);
        int   r2 = __ldg(&src[j + 2]); int   r3 = __ldg(&src[j + 3]);
        float w0 = __ldg(&wgt[j]);     float w1 = __ldg(&wgt[j + 1]);
        float w2 = __ldg(&wgt[j + 2]); float w3 = __ldg(&wgt[j + 3]);
        uint2 u0 = __ldg(&hb[(size_t)r0 * 32 + lane]);
        uint2 u1 = __ldg(&hb[(size_t)r1 * 32 + lane]);
        uint2 u2 = __ldg(&hb[(size_t)r2 * 32 + lane]);
        uint2 u3 = __ldg(&hb[(size_t)r3 * 32 + lane]);
        bf2acc(u0, w0, a);
        bf2acc(u1, w1, a2);
        bf2acc(u2, w2, a3);
        bf2acc(u3, w3, a4);
    }
    for (; j < e; j++) {
        int   r0 = __ldg(&src[j]);
        float w0 = __ldg(&wgt[j]);
        bf2acc(__ldg(&hb[(size_t)r0 * 32 + lane]), w0, a);
    }
    float4 b = __ldg(&((const float4*)bias)[lane]);
    a.x = fmaxf(a.x + a2.x + a3.x + a4.x + b.x, 0.f);
    a.y = fmaxf(a.y + a2.y + a3.y + a4.y + b.y, 0.f);
    a.z = fmaxf(a.z + a2.z + a3.z + a4.z + b.z, 0.f);
    a.w = fmaxf(a.w + a2.w + a3.w + a4.w + b.w, 0.f);
    ((float4*)acc)[(size_t)w * 32 + lane] = a;
}

// ---------------- segment boundaries from sorted batch ----------------
__global__ void k_bounds(const int* __restrict__ batch, int* __restrict__ gs,
                         int* __restrict__ ge, int n) {
    int i = blockIdx.x * blockDim.x + threadIdx.x;
    if (i >= n) return;
    int b = batch[i];
    if (i == 0 || batch[i - 1] != b) gs[b] = i;
    if (i == n - 1 || batch[i + 1] != b) ge[b] = i + 1;
}

// ---------------- chunked max pool (values >= 0; int atomicMax) ----------------
__global__ __launch_bounds__(128) void k_pool(const float* __restrict__ acc,
                                              const int* __restrict__ gs,
                                              const int* __restrict__ ge,
                                              float* __restrict__ pool) {
    int g = blockIdx.x;
    int chunk = blockIdx.y;
    int f = threadIdx.x;
    int s = gs[g], e = ge[g];
    int len = e - s;
    int per = (len + POOL_CHUNKS - 1) / POOL_CHUNKS;
    int cs = s + chunk * per;
    int ce = min(cs + per, e);
    if (cs >= ce) return;
    float m = 0.0f;
    for (int n = cs; n < ce; n++)
        m = fmaxf(m, acc[(size_t)n * D + f]);
    atomicMax((int*)&pool[g * D + f], __float_as_int(m));
}

// ---------------- head: z0 = relu(pool @ lin0_w + lin0_b) ----------------
__global__ void k_head1(const float* __restrict__ pool, const float* __restrict__ W,
                        const float* __restrict__ b, float* __restrict__ z0) {
    __shared__ float p[128];
    int g = blockIdx.x;
    int j = threadIdx.x;
    p[j] = pool[g * D + j];
    __syncthreads();
    float acc = b[j];
    for (int k = 0; k < 128; k++)
        acc = fmaf(p[k], __ldg(&W[k * 128 + j]), acc);
    z0[g * D + j] = fmaxf(acc, 0.f);
}

// ---------------- head: out = log_softmax(relu(z0 @ lin1_w + lin1_b)) ----------------
__global__ void k_head2(const float* __restrict__ z0, const float* __restrict__ W,
                        const float* __restrict__ b, float* __restrict__ out) {
    __shared__ float z[128];
    int g = blockIdx.x;
    int t = threadIdx.x;
#pragma unroll
    for (int i = 0; i < 4; i++) z[t + 32 * i] = z0[g * D + t + 32 * i];
    __syncwarp();
    float acc = 0.f;
    if (t < N_CLASSES) {
        acc = b[t];
        for (int k = 0; k < 128; k++)
            acc = fmaf(z[k], __ldg(&W[k * N_CLASSES + t]), acc);
        acc = fmaxf(acc, 0.f);
    }
    float vmax = (t < N_CLASSES) ? acc : -3.402823466e38f;
#pragma unroll
    for (int o = 16; o > 0; o >>= 1)
        vmax = fmaxf(vmax, __shfl_xor_sync(0xffffffff, vmax, o));
    float e = (t < N_CLASSES) ? expf(acc - vmax) : 0.f;
    float s = e;
#pragma unroll
    for (int o = 16; o > 0; o >>= 1)
        s += __shfl_xor_sync(0xffffffff, s, o);
    if (t < N_CLASSES)
        out[g * N_CLASSES + t] = acc - vmax - logf(s);
}

// ---------------- launch ----------------
extern "C" void kernel_launch(void* const* d_in, const int* in_sizes, int n_in,
                              void* d_out, int out_size) {
    const float* x = 0; const int* ei = 0; const int* batch = 0;
    const float* w16k[3] = {0,0,0}; int nw = 0;
    const float* b128[3] = {0,0,0}; int nb = 0;
    const float* lin1_w = 0; const float* lin1_b = 0;
    for (int i = 0; i < n_in; i++) {
        int s = in_sizes[i];
        if      (s == N_NODES * D)      x      = (const float*)d_in[i];
        else if (s == 2 * N_EDGES)      ei     = (const int*)  d_in[i];
        else if (s == N_NODES)          batch  = (const int*)  d_in[i];
        else if (s == D * D)            { if (nw < 3) w16k[nw++] = (const float*)d_in[i]; }
        else if (s == D)                { if (nb < 3) b128[nb++] = (const float*)d_in[i]; }
        else if (s == D * N_CLASSES)    lin1_w = (const float*)d_in[i];
        else if (s == N_CLASSES)        lin1_b = (const float*)d_in[i];
    }
    const float* conv0_w = w16k[0];
    const float* conv1_w = w16k[1];
    const float* lin0_w  = w16k[2];
    const float* conv0_b = b128[0];
    const float* conv1_b = b128[1];
    const float* lin0_b  = b128[2];
    float* out = (float*)d_out;

    // Runtime addresses for ALL scratch (symbol addressing in device code broken here).
    static __nv_bfloat162* p_hb = 0; static float* p_acc = 0; static int* p_ind = 0;
    static float* p_dinv = 0; static int* p_off = 0; static int* p_cur = 0;
    static int* p_src = 0; static float* p_wgt = 0; static int* p_part = 0;
    static float* p_pool = 0; static float* p_z0 = 0;
    static int* p_gs = 0; static int* p_ge = 0;
    static int gemm_smem = (64 + 128) * LDSP * 4;
    if (!p_hb) {
        cudaGetSymbolAddress((void**)&p_hb,   g_hb);
        cudaGetSymbolAddress((void**)&p_acc,  g_accx);
        cudaGetSymbolAddress((void**)&p_ind,  g_indeg);
        cudaGetSymbolAddress((void**)&p_dinv, g_dinvx);
        cudaGetSymbolAddress((void**)&p_off,  g_offx);
        cudaGetSymbolAddress((void**)&p_cur,  g_curx);
        cudaGetSymbolAddress((void**)&p_src,  g_srcx);
        cudaGetSymbolAddress((void**)&p_wgt,  g_wgtx);
        cudaGetSymbolAddress((void**)&p_part, g_partx);
        cudaGetSymbolAddress((void**)&p_pool, g_poolx);
        cudaGetSymbolAddress((void**)&p_z0,   g_z0x);
        cudaGetSymbolAddress((void**)&p_gs,   g_startx);
        cudaGetSymbolAddress((void**)&p_ge,   g_endx);
        cudaFuncSetAttribute(k_gemm_tc, cudaFuncAttributeMaxDynamicSharedMemorySize,
                             gemm_smem);
    }

    const int T = 256;
    const int gemm_blocks = (N_NODES + 63) / 64;
    const int gath_blocks = (N_NODES * 32 + T - 1) / T;

    // CSR build (parallel scan)
    k_seed    <<<(N_NODES + T - 1) / T, T>>>(p_ind, p_cur, p_pool, N_NODES);
    k_count   <<<(N_EDGES + T - 1) / T, T>>>(ei, p_ind, N_EDGES);
    k_dinv    <<<(N_NODES + T - 1) / T, T>>>(p_ind, p_dinv, N_NODES);
    k_part    <<<SCAN_NBLK, SCAN_B>>>(p_ind, p_part, N_NODES);
    k_scanpart<<<1, SCAN_B>>>(p_part, p_off, SCAN_NBLK, N_NODES);
    k_off     <<<SCAN_NBLK, SCAN_B>>>(p_ind, p_part, p_off, N_NODES);
    k_fill    <<<(N_EDGES + T - 1) / T, T>>>(ei, p_off, p_cur, p_src, p_wgt, p_dinv, N_EDGES);
    k_bounds  <<<(N_NODES + T - 1) / T, T>>>(batch, p_gs, p_ge, N_NODES);

    // conv0: hb = bf16(x@w0) ; acc = relu(agg(hb) + b0)
    k_gemm_tc<<<gemm_blocks, T, gemm_smem>>>(x, conv0_w, p_hb, N_NODES);
    k_gather <<<gath_blocks, T>>>(p_hb, p_acc, p_off, p_src, p_wgt, p_ind, conv0_b, N_NODES);

    // conv1
    k_gemm_tc<<<gemm_blocks, T, gemm_smem>>>(p_acc, conv1_w, p_hb, N_NODES);
    k_gather <<<gath_blocks, T>>>(p_hb, p_acc, p_off, p_src, p_wgt, p_ind, conv1_b, N_NODES);

    // pool + head
    dim3 pg(N_GRAPHS, POOL_CHUNKS);
    k_pool<<<pg, 128>>>(p_acc, p_gs, p_ge, p_pool);
    k_head1<<<N_GRAPHS, 128>>>(p_pool, lin0_w, lin0_b, p_z0);
    k_head2<<<N_GRAPHS, 32>>>(p_z0, lin1_w, lin1_b, out);
}